// round 5
// baseline (speedup 1.0000x reference)
#include <cuda_runtime.h>
#include <math.h>

#define NCTA 32

// ---------------- persistent scratch (static __device__, no allocations) ----------------
struct Scratch {
  unsigned ctr;                 // single epoch barrier counter
  float hA[2][2][256];          // tier1 layer1 input-hidden  [parity][b][unit]
  float hM[2][2][256];          // tier1 layer1 output h (feeds layer2)
  float hB[2][2][256];          // tier1 layer2 input-hidden
  float h2A[2][2][128];         // tier2 layer1 input-hidden
  float h2M[2][2][128];         // tier2 layer1 output h
  float h2B[2][2][128];         // tier2 layer2 input-hidden
  float fo[32][2][256];         // first_out, live frames 0..31
  float inp2[128][2][256];      // tier2 inputs, live rows 0..127
  float so[128][2][128];        // second_out, live rows 0..127
};
__device__ Scratch g_s;

__device__ __forceinline__ float sigf(float v) { return 1.0f / (1.0f + expf(-v)); }

// epoch-target global barrier across NCTA co-resident CTAs
__device__ __forceinline__ void gbar(int target) {
  __threadfence();
  __syncthreads();
  if (threadIdx.x == 0) {
    atomicAdd(&g_s.ctr, 1u);
    while (*((volatile unsigned*)&g_s.ctr) < (unsigned)target) { }
    __threadfence();
  }
  __syncthreads();
}

// ---------------- init: zero counter + initial hidden state ----------------
__global__ void gen_init_kernel() {
  int tid = threadIdx.x;
  if (tid == 0) g_s.ctr = 0u;
  float* a = &g_s.hA[0][0][0];
  float* b = &g_s.hB[0][0][0];
  for (int i = tid; i < 1024; i += blockDim.x) { a[i] = 0.f; b[i] = 0.f; }
  float* c = &g_s.h2A[0][0][0];
  float* d = &g_s.h2B[0][0][0];
  for (int i = tid; i < 512; i += blockDim.x) { c[i] = 0.f; d[i] = 0.f; }
}

// =====================================================================
// Tier 1 (frames 0..31, 256 steps) + Tier 2 (steps 0..127), persistent.
// 32 CTAs x 512 threads. Tier1: CTA owns 8 hidden units (32 gate-rows),
// 16 threads per (row) computing both batches. Tier2: CTA owns 4 units.
// Cross-CTA hidden exchange through L2 (__stcg/__ldcg) + global barrier.
// =====================================================================
__global__ void __launch_bounds__(512) gen_tier12_kernel(
  const float* __restrict__ x,
  const float* __restrict__ t1_Wih1, const float* __restrict__ t1_Whh1,
  const float* __restrict__ t1_bih1, const float* __restrict__ t1_bhh1,
  const float* __restrict__ t1_Wih2, const float* __restrict__ t1_Whh2,
  const float* __restrict__ t1_bih2, const float* __restrict__ t1_bhh2,
  const float* __restrict__ W2in,    const float* __restrict__ W2hid,
  const float* __restrict__ t2_Wih1, const float* __restrict__ t2_Whh1,
  const float* __restrict__ t2_bih1, const float* __restrict__ t2_bhh1,
  const float* __restrict__ t2_Wih2, const float* __restrict__ t2_Whh2,
  const float* __restrict__ t2_bih2, const float* __restrict__ t2_bhh2)
{
  const int cta = blockIdx.x;
  const int tid = threadIdx.x;
  const int grp = tid >> 4;      // 0..31
  const int l16 = tid & 15;

  __shared__ float sA[2][256];   // h1prev staging
  __shared__ float sB[2][256];   // h2prev staging
  __shared__ float sM[2][256];   // h1 (mid) staging
  __shared__ float sg[32][2];    // gate pre-activations
  __shared__ float cell1[8][2], cell2[8][2];

  if (tid < 16) { cell1[tid >> 1][tid & 1] = 0.f; cell2[tid >> 1][tid & 1] = 0.f; }

  int nbar = 0;

  // ---------------- tier 1 ----------------
  // row mapping: grp -> unit uu = grp>>2 (0..7), gate = grp&3 (i,f,g,o)
  {
    const int uu   = grp >> 2;
    const int gate = grp & 3;
    const int unit = cta * 8 + uu;
    const int row  = gate * 256 + unit;

    float w1r[16], wi2[16], wh2[16];   // per-frame register weight cache
    float bs1 = 0.f, wx1 = 0.f, bs2 = 0.f;

    for (int s = 0; s < 256; ++s) {
      const int p = s & 1, pn = p ^ 1;
      const int f = s >> 3, sin = s & 7;

      if (sin == 0) {
        // load this frame's weight slices into registers (reused 8 steps)
        size_t rb = (size_t)f * 1024 + row;
        const float* W  = t1_Whh1 + rb * 256 + l16 * 16;
        const float* Wi = t1_Wih2 + rb * 256 + l16 * 16;
        const float* Wh = t1_Whh2 + rb * 256 + l16 * 16;
        #pragma unroll
        for (int j = 0; j < 16; j += 4) {
          float4 v = *(const float4*)(W  + j); w1r[j]=v.x; w1r[j+1]=v.y; w1r[j+2]=v.z; w1r[j+3]=v.w;
          float4 a = *(const float4*)(Wi + j); wi2[j]=a.x; wi2[j+1]=a.y; wi2[j+2]=a.z; wi2[j+3]=a.w;
          float4 h = *(const float4*)(Wh + j); wh2[j]=h.x; wh2[j+1]=h.y; wh2[j+2]=h.z; wh2[j+3]=h.w;
        }
        if (l16 == 0) {
          bs1 = t1_bih1[rb] + t1_bhh1[rb];
          wx1 = t1_Wih1[rb];
          bs2 = t1_bih2[rb] + t1_bhh2[rb];
        }
      }

      // stage h1prev / h2prev (cross-CTA, from L2)
      { int b = tid >> 8, u = tid & 255;
        sA[b][u] = __ldcg(&g_s.hA[p][b][u]);
        sB[b][u] = __ldcg(&g_s.hB[p][b][u]); }
      __syncthreads();

      // ---- layer 1 gate: Whh1_row . h1prev (+ x*Wih1 + biases) ----
      {
        float a0 = 0.f, a1 = 0.f;
        #pragma unroll
        for (int j = 0; j < 16; ++j) {
          int k = l16 * 16 + j;
          a0 += w1r[j] * sA[0][k];
          a1 += w1r[j] * sA[1][k];
        }
        #pragma unroll
        for (int o = 8; o; o >>= 1) {
          a0 += __shfl_down_sync(0xffffffffu, a0, o, 16);
          a1 += __shfl_down_sync(0xffffffffu, a1, o, 16);
        }
        if (l16 == 0) {
          sg[grp][0] = a0 + bs1 + wx1 * x[2 * s + 0];
          sg[grp][1] = a1 + bs1 + wx1 * x[2 * s + 1];
        }
      }
      __syncthreads();

      if (tid < 16) {
        int cu = tid >> 1, bb = tid & 1;
        float gi = sg[cu * 4 + 0][bb], gf = sg[cu * 4 + 1][bb];
        float gg = sg[cu * 4 + 2][bb], go = sg[cu * 4 + 3][bb];
        float c  = cell1[cu][bb];
        float cn = sigf(gf) * c + sigf(gi) * tanhf(gg);
        float hn = sigf(go) * tanhf(cn);
        cell1[cu][bb] = (sin == 7) ? 0.f : cn;
        int un = cta * 8 + cu;
        __stcg(&g_s.hM[p][bb][un], hn);
        __stcg(&g_s.hA[pn][bb][un], (sin == 7) ? cn : hn);  // frame end: next h0 = final cell
      }
      gbar(++nbar * NCTA);

      // stage full h1 (mid)
      { int b = tid >> 8, u = tid & 255; sM[b][u] = __ldcg(&g_s.hM[p][b][u]); }
      __syncthreads();

      // ---- layer 2 gate: Wih2_row . h1 + Whh2_row . h2prev ----
      {
        float a0 = 0.f, a1 = 0.f;
        #pragma unroll
        for (int j = 0; j < 16; ++j) {
          int k = l16 * 16 + j;
          a0 += wi2[j] * sM[0][k] + wh2[j] * sB[0][k];
          a1 += wi2[j] * sM[1][k] + wh2[j] * sB[1][k];
        }
        #pragma unroll
        for (int o = 8; o; o >>= 1) {
          a0 += __shfl_down_sync(0xffffffffu, a0, o, 16);
          a1 += __shfl_down_sync(0xffffffffu, a1, o, 16);
        }
        if (l16 == 0) { sg[grp][0] = a0 + bs2; sg[grp][1] = a1 + bs2; }
      }
      __syncthreads();

      if (tid < 16) {
        int cu = tid >> 1, bb = tid & 1;
        float gi = sg[cu * 4 + 0][bb], gf = sg[cu * 4 + 1][bb];
        float gg = sg[cu * 4 + 2][bb], go = sg[cu * 4 + 3][bb];
        float c  = cell2[cu][bb];
        float cn = sigf(gf) * c + sigf(gi) * tanhf(gg);
        float hn = sigf(go) * tanhf(cn);
        cell2[cu][bb] = (sin == 7) ? 0.f : cn;
        int un = cta * 8 + cu;
        __stcg(&g_s.hB[pn][bb][un], (sin == 7) ? cn : hn);
        if (sin == 7) __stcg(&g_s.fo[f][bb][un], hn);       // first_out = last-step h2
      }
      gbar(++nbar * NCTA);
    }
  }

  // ---------------- inp2 precompute (all 128 live rows) ----------------
  // inp2[r][b][u] = (x[4r+b]+x[4r+2+b]) * W2in[u] + W2hid[u,:] . fo[r/4][b]
  for (int idx = tid; idx < 128 * 16; idx += 512) {
    int r = idx >> 4, q = idx & 15;
    int u = cta * 8 + (q >> 1), bb = q & 1;
    const float* Wr = W2hid + u * 256;
    const float* fr = &g_s.fo[r >> 2][bb][0];
    float acc = 0.f;
    #pragma unroll 4
    for (int j = 0; j < 256; j += 4) {
      float4 w = *(const float4*)(Wr + j);
      acc += w.x * __ldcg(fr + j)     + w.y * __ldcg(fr + j + 1)
           + w.z * __ldcg(fr + j + 2) + w.w * __ldcg(fr + j + 3);
    }
    float xs = x[4 * r + bb] + x[4 * r + 2 + bb];
    __stcg(&g_s.inp2[r][bb][u], xs * W2in[u] + acc);
  }
  gbar(++nbar * NCTA);

  // ---------------- tier 2 (128 live steps) ----------------
  // task = grp (0..31): bb = task&1, rl = task>>1 (0..15), gate = rl&3, ul = rl>>2
  {
    const int t2b   = grp & 1;
    const int rl    = grp >> 1;
    const int gate2 = rl & 3;
    const int ul    = rl >> 2;
    const int unit2 = cta * 4 + ul;
    const int row2  = gate2 * 128 + unit2;

    __shared__ float t2i[2][256], t2a[2][128], t2bp[2][128], t2m[2][128];
    __shared__ float sg2[32];

    for (int r = 0; r < 128; ++r) {
      const int p = r & 1, pn = p ^ 1;
      const size_t base = (size_t)r * 512 + row2;

      // stage
      { int b = tid >> 8, u = tid & 255; t2i[b][u] = __ldcg(&g_s.inp2[r][b][u]); }
      if (tid < 256) { int b = tid >> 7, u = tid & 127;
        t2a[b][u]  = __ldcg(&g_s.h2A[p][b][u]);
        t2bp[b][u] = __ldcg(&g_s.h2B[p][b][u]); }
      __syncthreads();

      // ---- layer 1: Wih1 . inp2 (256) + Whh1 . h1prev (128) ----
      {
        const float* Wi = t2_Wih1 + base * 256 + l16 * 16;
        const float* Wh = t2_Whh1 + base * 128 + l16 * 8;
        float a = 0.f;
        #pragma unroll
        for (int j = 0; j < 16; j += 4) {
          float4 v = *(const float4*)(Wi + j); int k = l16 * 16 + j;
          a += v.x * t2i[t2b][k] + v.y * t2i[t2b][k+1] + v.z * t2i[t2b][k+2] + v.w * t2i[t2b][k+3];
        }
        #pragma unroll
        for (int j = 0; j < 8; j += 4) {
          float4 v = *(const float4*)(Wh + j); int k = l16 * 8 + j;
          a += v.x * t2a[t2b][k] + v.y * t2a[t2b][k+1] + v.z * t2a[t2b][k+2] + v.w * t2a[t2b][k+3];
        }
        #pragma unroll
        for (int o = 8; o; o >>= 1) a += __shfl_down_sync(0xffffffffu, a, o, 16);
        if (l16 == 0) sg2[grp] = a + t2_bih1[base] + t2_bhh1[base];
      }
      __syncthreads();

      if (tid < 8) {
        int cu = tid >> 1, bb = tid & 1;
        // tier2 cell is always 0 at step start (1-step frames): cn = sig(i)*tanh(g)
        float gi = sg2[((cu * 4 + 0) * 2) + bb];
        float gg = sg2[((cu * 4 + 2) * 2) + bb];
        float go = sg2[((cu * 4 + 3) * 2) + bb];
        float cn = sigf(gi) * tanhf(gg);
        float hn = sigf(go) * tanhf(cn);
        int un = cta * 4 + cu;
        __stcg(&g_s.h2M[p][bb][un], hn);
        __stcg(&g_s.h2A[pn][bb][un], cn);   // next h0 = cell
      }
      gbar(++nbar * NCTA);

      if (tid < 256) { int b = tid >> 7, u = tid & 127; t2m[b][u] = __ldcg(&g_s.h2M[p][b][u]); }
      __syncthreads();

      // ---- layer 2: Wih2 . h1 (128) + Whh2 . h2prev (128) ----
      {
        const float* Wi = t2_Wih2 + base * 128 + l16 * 8;
        const float* Wh = t2_Whh2 + base * 128 + l16 * 8;
        float a = 0.f;
        #pragma unroll
        for (int j = 0; j < 8; j += 4) {
          float4 vi = *(const float4*)(Wi + j);
          float4 vh = *(const float4*)(Wh + j);
          int k = l16 * 8 + j;
          a += vi.x * t2m[t2b][k]  + vi.y * t2m[t2b][k+1]  + vi.z * t2m[t2b][k+2]  + vi.w * t2m[t2b][k+3];
          a += vh.x * t2bp[t2b][k] + vh.y * t2bp[t2b][k+1] + vh.z * t2bp[t2b][k+2] + vh.w * t2bp[t2b][k+3];
        }
        #pragma unroll
        for (int o = 8; o; o >>= 1) a += __shfl_down_sync(0xffffffffu, a, o, 16);
        if (l16 == 0) sg2[grp] = a + t2_bih2[base] + t2_bhh2[base];
      }
      __syncthreads();

      if (tid < 8) {
        int cu = tid >> 1, bb = tid & 1;
        float gi = sg2[((cu * 4 + 0) * 2) + bb];
        float gg = sg2[((cu * 4 + 2) * 2) + bb];
        float go = sg2[((cu * 4 + 3) * 2) + bb];
        float cn = sigf(gi) * tanhf(gg);
        float hn = sigf(go) * tanhf(cn);
        int un = cta * 4 + cu;
        __stcg(&g_s.h2B[pn][bb][un], cn);    // next h0 = cell
        __stcg(&g_s.so[r][bb][un], hn);      // second_out
      }
      gbar(++nbar * NCTA);
    }
  }
}

// =====================================================================
// Tier 3: 512 independent MLPs (512->1024->1024->1), one CTA each.
// DRAM-streaming bound (3.2 GB). Warp-per-row, float4-coalesced.
// out[s] = softmax over batch of relu(y)[b=1] = sigmoid(y1 - y0).
// =====================================================================
__global__ void __launch_bounds__(512, 2) gen_tier3_kernel(
  const float* __restrict__ x,
  const float* __restrict__ W3in, const float* __restrict__ W3hid,
  const float* __restrict__ W1,   const float* __restrict__ b1,
  const float* __restrict__ W2,   const float* __restrict__ b2,
  const float* __restrict__ W3,   const float* __restrict__ b3,
  float* __restrict__ out)
{
  const int s = blockIdx.x;
  const int tid = threadIdx.x;
  const int lane = tid & 31, w = tid >> 5;

  __shared__ float si[2][512];
  __shared__ float sh1[2][1024];
  __shared__ float sh2[2][1024];
  __shared__ float sq[2][128];
  __shared__ float yv[2];

  if (tid < 256) { int b = tid >> 7, u = tid & 127; sq[b][u] = g_s.so[s >> 2][b][u]; }
  __syncthreads();

  const float x0 = x[2 * s], x1 = x[2 * s + 1];

  // inp3[b][d] = x_b * W3in[d] + W3hid[d,:] . so[s/4][b]
  {
    const float* Wr = W3hid + tid * 128;
    float a0 = 0.f, a1 = 0.f;
    #pragma unroll 4
    for (int j = 0; j < 128; j += 4) {
      float4 v = *(const float4*)(Wr + j);
      a0 += v.x * sq[0][j] + v.y * sq[0][j+1] + v.z * sq[0][j+2] + v.w * sq[0][j+3];
      a1 += v.x * sq[1][j] + v.y * sq[1][j+1] + v.z * sq[1][j+2] + v.w * sq[1][j+3];
    }
    float wv = W3in[tid];
    si[0][tid] = x0 * wv + a0;
    si[1][tid] = x1 * wv + a1;
  }
  __syncthreads();

  // h1 = relu(W1[s] @ inp3 + b1[s])   (1024 x 512)
  {
    const float* W1s = W1 + (size_t)s * 1024 * 512;
    for (int o = w; o < 1024; o += 16) {
      const float* Wr = W1s + (size_t)o * 512;
      float a0 = 0.f, a1 = 0.f;
      #pragma unroll
      for (int k = 0; k < 4; ++k) {
        int ix = k * 128 + lane * 4;
        float4 v = *(const float4*)(Wr + ix);
        a0 += v.x * si[0][ix] + v.y * si[0][ix+1] + v.z * si[0][ix+2] + v.w * si[0][ix+3];
        a1 += v.x * si[1][ix] + v.y * si[1][ix+1] + v.z * si[1][ix+2] + v.w * si[1][ix+3];
      }
      #pragma unroll
      for (int off = 16; off; off >>= 1) {
        a0 += __shfl_down_sync(0xffffffffu, a0, off);
        a1 += __shfl_down_sync(0xffffffffu, a1, off);
      }
      if (lane == 0) {
        float bb = b1[s * 1024 + o];
        sh1[0][o] = fmaxf(a0 + bb, 0.f);
        sh1[1][o] = fmaxf(a1 + bb, 0.f);
      }
    }
  }
  __syncthreads();

  // h2 = relu(W2[s] @ h1 + b2[s])   (1024 x 1024)
  {
    const float* W2s = W2 + (size_t)s * 1024 * 1024;
    for (int o = w; o < 1024; o += 16) {
      const float* Wr = W2s + (size_t)o * 1024;
      float a0 = 0.f, a1 = 0.f;
      #pragma unroll
      for (int k = 0; k < 8; ++k) {
        int ix = k * 128 + lane * 4;
        float4 v = *(const float4*)(Wr + ix);
        a0 += v.x * sh1[0][ix] + v.y * sh1[0][ix+1] + v.z * sh1[0][ix+2] + v.w * sh1[0][ix+3];
        a1 += v.x * sh1[1][ix] + v.y * sh1[1][ix+1] + v.z * sh1[1][ix+2] + v.w * sh1[1][ix+3];
      }
      #pragma unroll
      for (int off = 16; off; off >>= 1) {
        a0 += __shfl_down_sync(0xffffffffu, a0, off);
        a1 += __shfl_down_sync(0xffffffffu, a1, off);
      }
      if (lane == 0) {
        float bb = b2[s * 1024 + o];
        sh2[0][o] = fmaxf(a0 + bb, 0.f);
        sh2[1][o] = fmaxf(a1 + bb, 0.f);
      }
    }
  }
  __syncthreads();

  // y[b] = relu(W3[s] . h2[b] + b3[s]); warp 0 -> b0, warp 1 -> b1
  if (w < 2) {
    const float* Wr = W3 + (size_t)s * 1024;
    float a = 0.f;
    for (int j = lane * 4; j < 1024; j += 128) {
      float4 v = *(const float4*)(Wr + j);
      a += v.x * sh2[w][j] + v.y * sh2[w][j+1] + v.z * sh2[w][j+2] + v.w * sh2[w][j+3];
    }
    #pragma unroll
    for (int off = 16; off; off >>= 1) a += __shfl_down_sync(0xffffffffu, a, off);
    if (lane == 0) yv[w] = fmaxf(a + b3[s], 0.f);
  }
  __syncthreads();

  if (tid == 0) {
    // softmax over batch dim (size 2), keep batch index 1
    out[s] = 1.0f / (1.0f + expf(yv[0] - yv[1]));
  }
}

extern "C" void kernel_launch(void* const* d_in, const int* in_sizes, int n_in,
                              void* d_out, int out_size) {
  const float* x        = (const float*)d_in[0];
  const float* t1_Wih1  = (const float*)d_in[1];
  const float* t1_Whh1  = (const float*)d_in[2];
  const float* t1_bih1  = (const float*)d_in[3];
  const float* t1_bhh1  = (const float*)d_in[4];
  const float* t1_Wih2  = (const float*)d_in[5];
  const float* t1_Whh2  = (const float*)d_in[6];
  const float* t1_bih2  = (const float*)d_in[7];
  const float* t1_bhh2  = (const float*)d_in[8];
  const float* W2in     = (const float*)d_in[9];
  const float* W2hid    = (const float*)d_in[10];
  const float* t2_Wih1  = (const float*)d_in[11];
  const float* t2_Whh1  = (const float*)d_in[12];
  const float* t2_bih1  = (const float*)d_in[13];
  const float* t2_bhh1  = (const float*)d_in[14];
  const float* t2_Wih2  = (const float*)d_in[15];
  const float* t2_Whh2  = (const float*)d_in[16];
  const float* t2_bih2  = (const float*)d_in[17];
  const float* t2_bhh2  = (const float*)d_in[18];
  const float* W3in     = (const float*)d_in[19];
  const float* W3hid    = (const float*)d_in[20];
  const float* t3_W1    = (const float*)d_in[21];
  const float* t3_b1    = (const float*)d_in[22];
  const float* t3_W2    = (const float*)d_in[23];
  const float* t3_b2    = (const float*)d_in[24];
  const float* t3_W3    = (const float*)d_in[25];
  const float* t3_b3    = (const float*)d_in[26];
  float* out = (float*)d_out;

  gen_init_kernel<<<1, 256>>>();
  gen_tier12_kernel<<<NCTA, 512>>>(
      x, t1_Wih1, t1_Whh1, t1_bih1, t1_bhh1, t1_Wih2, t1_Whh2, t1_bih2, t1_bhh2,
      W2in, W2hid,
      t2_Wih1, t2_Whh1, t2_bih1, t2_bhh1, t2_Wih2, t2_Whh2, t2_bih2, t2_bhh2);
  gen_tier3_kernel<<<512, 512>>>(x, W3in, W3hid, t3_W1, t3_b1, t3_W2, t3_b2, t3_W3, t3_b3, out);
}

// round 6
// speedup vs baseline: 1.3755x; 1.3755x over previous
#include <cuda_runtime.h>
#include <math.h>

#define NCHAIN 32
#define NT3    512
#define NBLK   (NCHAIN + NT3)

// ---------------- persistent scratch (static __device__, no allocations) ----------------
struct Scratch {
  unsigned flags[NCHAIN * 32];  // barrier flag per chain CTA, 128B apart
  unsigned so_done;             // tier2 progress counter (for tier3 consumers)
  float hA[2][2][256];          // tier1 L1 carry  [interval parity][b][unit]
  float hM[2][2][256];          // tier1 L1 real h (feeds L2)
  float hB[2][2][256];          // tier1 L2 carry/real h
  float h2A[2][2][128];         // tier2 L1 carry
  float h2M[2][2][128];         // tier2 L1 real h
  float h2B[2][2][128];         // tier2 L2 carry
  float fo[32][2][256];         // first_out, live frames 0..31
  float inp2[128][2][256];      // tier2 inputs, live rows 0..127
  float so[128][2][128];        // second_out, live rows 0..127
};
__device__ Scratch g_s;

__device__ __forceinline__ float sigf(float v) { return 1.0f / (1.0f + __expf(-v)); }
__device__ __forceinline__ float tanhfast(float v) {
  float r; asm("tanh.approx.f32 %0, %1;" : "=f"(r) : "f"(v)); return r;
}

// all-to-all flag barrier across NCHAIN chain CTAs
__device__ __forceinline__ void gbar(int cta, int tid, unsigned e) {
  __syncthreads();
  __threadfence();
  if (tid == 0) *(volatile unsigned*)&g_s.flags[cta * 32] = e;
  if (tid < NCHAIN) {
    volatile unsigned* f = &g_s.flags[tid * 32];
    while (*f < e) { }
  }
  __threadfence();
  __syncthreads();
}

// ---------------- init: zero flags, counter, initial hidden/carry state ----------------
__global__ void gen_init_kernel() {
  int tid = threadIdx.x;
  for (int i = tid; i < NCHAIN * 32; i += blockDim.x) g_s.flags[i] = 0u;
  if (tid == 0) g_s.so_done = 0u;
  float* p1 = &g_s.hA[0][0][0];   // hA,hM,hB contiguous: 3*1024 floats
  for (int i = tid; i < 3 * 1024; i += blockDim.x) p1[i] = 0.f;
  float* p2 = &g_s.h2A[0][0][0];  // h2A,h2M,h2B contiguous: 3*512 floats
  for (int i = tid; i < 3 * 512; i += blockDim.x) p2[i] = 0.f;
}

// =====================================================================
// Fused kernel. Blocks 0..31: tier1+tier2 chain (pipelined, 1 barrier
// per LSTM step). Blocks 32..543: tier3 MLPs gated on so_done.
// =====================================================================
__global__ void __launch_bounds__(512) gen_fused_kernel(
  const float* __restrict__ x,
  const float* __restrict__ t1_Wih1, const float* __restrict__ t1_Whh1,
  const float* __restrict__ t1_bih1, const float* __restrict__ t1_bhh1,
  const float* __restrict__ t1_Wih2, const float* __restrict__ t1_Whh2,
  const float* __restrict__ t1_bih2, const float* __restrict__ t1_bhh2,
  const float* __restrict__ W2in,    const float* __restrict__ W2hid,
  const float* __restrict__ t2_Wih1, const float* __restrict__ t2_Whh1,
  const float* __restrict__ t2_bih1, const float* __restrict__ t2_bhh1,
  const float* __restrict__ t2_Wih2, const float* __restrict__ t2_Whh2,
  const float* __restrict__ t2_bih2, const float* __restrict__ t2_bhh2,
  const float* __restrict__ W3in,    const float* __restrict__ W3hid,
  const float* __restrict__ W1,      const float* __restrict__ b1,
  const float* __restrict__ W2,      const float* __restrict__ b2,
  const float* __restrict__ W3,      const float* __restrict__ b3,
  float* __restrict__ out)
{
  const int tid = threadIdx.x;

  if (blockIdx.x >= NCHAIN) {
    // ================== TIER 3 MLP path ==================
    const int s = blockIdx.x - NCHAIN;
    const int lane = tid & 31, w = tid >> 5;

    __shared__ float si[2][512];
    __shared__ float sh1[2][1024];
    __shared__ float sh2[2][1024];
    __shared__ float sq[2][128];
    __shared__ float yv[2];

    // wait for second_out[s>>2]
    const unsigned want = (unsigned)(s >> 2) + 1u;
    if (tid == 0) {
      while (*(volatile unsigned*)&g_s.so_done < want) __nanosleep(256);
    }
    __syncthreads();
    __threadfence();

    if (tid < 256) { int b = tid >> 7, u = tid & 127; sq[b][u] = __ldcg(&g_s.so[s >> 2][b][u]); }
    __syncthreads();

    const float x0 = x[2 * s], x1 = x[2 * s + 1];

    // inp3[b][d] = x_b * W3in[d] + W3hid[d,:] . so[s/4][b]
    {
      const float* Wr = W3hid + tid * 128;
      float a0 = 0.f, a1 = 0.f;
      #pragma unroll 4
      for (int j = 0; j < 128; j += 4) {
        float4 v = *(const float4*)(Wr + j);
        a0 += v.x * sq[0][j] + v.y * sq[0][j+1] + v.z * sq[0][j+2] + v.w * sq[0][j+3];
        a1 += v.x * sq[1][j] + v.y * sq[1][j+1] + v.z * sq[1][j+2] + v.w * sq[1][j+3];
      }
      float wv = W3in[tid];
      si[0][tid] = x0 * wv + a0;
      si[1][tid] = x1 * wv + a1;
    }
    __syncthreads();

    // h1 = relu(W1[s] @ inp3 + b1[s])   (1024 x 512)
    {
      const float* W1s = W1 + (size_t)s * 1024 * 512;
      for (int o = w; o < 1024; o += 16) {
        const float* Wr = W1s + (size_t)o * 512;
        float a0 = 0.f, a1 = 0.f;
        #pragma unroll
        for (int k = 0; k < 4; ++k) {
          int ix = k * 128 + lane * 4;
          float4 v = *(const float4*)(Wr + ix);
          a0 += v.x * si[0][ix] + v.y * si[0][ix+1] + v.z * si[0][ix+2] + v.w * si[0][ix+3];
          a1 += v.x * si[1][ix] + v.y * si[1][ix+1] + v.z * si[1][ix+2] + v.w * si[1][ix+3];
        }
        #pragma unroll
        for (int off = 16; off; off >>= 1) {
          a0 += __shfl_down_sync(0xffffffffu, a0, off);
          a1 += __shfl_down_sync(0xffffffffu, a1, off);
        }
        if (lane == 0) {
          float bb = b1[s * 1024 + o];
          sh1[0][o] = fmaxf(a0 + bb, 0.f);
          sh1[1][o] = fmaxf(a1 + bb, 0.f);
        }
      }
    }
    __syncthreads();

    // h2 = relu(W2[s] @ h1 + b2[s])   (1024 x 1024)
    {
      const float* W2s = W2 + (size_t)s * 1024 * 1024;
      for (int o = w; o < 1024; o += 16) {
        const float* Wr = W2s + (size_t)o * 1024;
        float a0 = 0.f, a1 = 0.f;
        #pragma unroll
        for (int k = 0; k < 8; ++k) {
          int ix = k * 128 + lane * 4;
          float4 v = *(const float4*)(Wr + ix);
          a0 += v.x * sh1[0][ix] + v.y * sh1[0][ix+1] + v.z * sh1[0][ix+2] + v.w * sh1[0][ix+3];
          a1 += v.x * sh1[1][ix] + v.y * sh1[1][ix+1] + v.z * sh1[1][ix+2] + v.w * sh1[1][ix+3];
        }
        #pragma unroll
        for (int off = 16; off; off >>= 1) {
          a0 += __shfl_down_sync(0xffffffffu, a0, off);
          a1 += __shfl_down_sync(0xffffffffu, a1, off);
        }
        if (lane == 0) {
          float bb = b2[s * 1024 + o];
          sh2[0][o] = fmaxf(a0 + bb, 0.f);
          sh2[1][o] = fmaxf(a1 + bb, 0.f);
        }
      }
    }
    __syncthreads();

    // y[b] = relu(W3[s] . h2[b] + b3[s])
    if (w < 2) {
      const float* Wr = W3 + (size_t)s * 1024;
      float a = 0.f;
      for (int j = lane * 4; j < 1024; j += 128) {
        float4 v = *(const float4*)(Wr + j);
        a += v.x * sh2[w][j] + v.y * sh2[w][j+1] + v.z * sh2[w][j+2] + v.w * sh2[w][j+3];
      }
      #pragma unroll
      for (int off = 16; off; off >>= 1) a += __shfl_down_sync(0xffffffffu, a, off);
      if (lane == 0) yv[w] = fmaxf(a + b3[s], 0.f);
    }
    __syncthreads();

    if (tid == 0) out[s] = 1.0f / (1.0f + expf(yv[0] - yv[1]));  // softmax over batch, keep b=1
    return;
  }

  // ================== CHAIN path (blocks 0..31) ==================
  const int cta = blockIdx.x;
  const int grp = tid >> 4;     // 0..31
  const int l16 = tid & 15;

  __shared__ float sA[2][256];  // staged hA (L1 carry)
  __shared__ float sM[2][256];  // staged hM (L1 real h)
  __shared__ float sB[2][256];  // staged hB (L2 carry)
  __shared__ float sg[32][2];
  __shared__ float cell1[8][2], cell2[8][2];
  __shared__ float t2i[2][256], t2a[2][128], t2m[2][128], t2bp[2][128];

  if (tid < 16) { cell1[tid >> 1][tid & 1] = 0.f; cell2[tid >> 1][tid & 1] = 0.f; }

  unsigned ep = 0;

  // ---------------- tier 1: intervals k=0..256, pipelined L1(k) || L2(k-1) ----------------
  {
    const int uu = grp >> 2, gate = grp & 3;
    const int unit = cta * 8 + uu;
    const int row  = gate * 256 + unit;

    float w1r[16], wi2[16], wh2[16];    // per-frame register weight cache
    float bs1 = 0.f, wx1 = 0.f, bs2 = 0.f;

    for (int k = 0; k <= 256; ++k) {
      const int p = k & 1, pn = p ^ 1;

      if (k < 256 && (k & 7) == 0) {
        // frame start: load this frame's weight slices (reused 8 steps)
        size_t rb = (size_t)(k >> 3) * 1024 + row;
        const float* Wa = t1_Whh1 + rb * 256 + l16 * 16;
        const float* Wi = t1_Wih2 + rb * 256 + l16 * 16;
        const float* Wh = t1_Whh2 + rb * 256 + l16 * 16;
        #pragma unroll
        for (int j = 0; j < 16; j += 4) {
          float4 v = *(const float4*)(Wa + j); w1r[j]=v.x; w1r[j+1]=v.y; w1r[j+2]=v.z; w1r[j+3]=v.w;
          float4 a = *(const float4*)(Wi + j); wi2[j]=a.x; wi2[j+1]=a.y; wi2[j+2]=a.z; wi2[j+3]=a.w;
          float4 h = *(const float4*)(Wh + j); wh2[j]=h.x; wh2[j+1]=h.y; wh2[j+2]=h.z; wh2[j+3]=h.w;
        }
        bs1 = __ldg(t1_bih1 + rb) + __ldg(t1_bhh1 + rb);
        wx1 = __ldg(t1_Wih1 + rb);
        bs2 = __ldg(t1_bih2 + rb) + __ldg(t1_bhh2 + rb);
      }

      // stage state published last interval
      { int b = tid >> 8, u = tid & 255;
        sA[b][u] = __ldcg(&g_s.hA[pn][b][u]);
        sM[b][u] = __ldcg(&g_s.hM[pn][b][u]);
        sB[b][u] = __ldcg(&g_s.hB[pn][b][u]); }
      __syncthreads();

      // ---- L1(k): Whh1_row . h1carry + x*Wih1 + biases ----
      if (k < 256) {
        float a0 = 0.f, a1 = 0.f;
        #pragma unroll
        for (int j = 0; j < 16; ++j) {
          int kk = l16 * 16 + j;
          a0 += w1r[j] * sA[0][kk];
          a1 += w1r[j] * sA[1][kk];
        }
        #pragma unroll
        for (int o = 8; o; o >>= 1) {
          a0 += __shfl_down_sync(0xffffffffu, a0, o, 16);
          a1 += __shfl_down_sync(0xffffffffu, a1, o, 16);
        }
        if (l16 == 0) {
          sg[grp][0] = a0 + bs1 + wx1 * x[2 * k + 0];
          sg[grp][1] = a1 + bs1 + wx1 * x[2 * k + 1];
        }
      }
      __syncthreads();
      if (k < 256 && tid < 16) {
        int cu = tid >> 1, bb = tid & 1, sin = k & 7;
        float gi = sg[cu*4+0][bb], gf = sg[cu*4+1][bb], gg = sg[cu*4+2][bb], go = sg[cu*4+3][bb];
        float c  = cell1[cu][bb];
        float cn = sigf(gf) * c + sigf(gi) * tanhfast(gg);
        float hn = sigf(go) * tanhfast(cn);
        cell1[cu][bb] = (sin == 7) ? 0.f : cn;
        int un = cta * 8 + cu;
        __stcg(&g_s.hM[p][bb][un], hn);
        __stcg(&g_s.hA[p][bb][un], (sin == 7) ? cn : hn);
      }
      __syncthreads();

      // ---- L2(k-1): Wih2_row . h1real + Whh2_row . h2carry ----
      if (k > 0) {
        float a0 = 0.f, a1 = 0.f;
        #pragma unroll
        for (int j = 0; j < 16; ++j) {
          int kk = l16 * 16 + j;
          a0 += wi2[j] * sM[0][kk] + wh2[j] * sB[0][kk];
          a1 += wi2[j] * sM[1][kk] + wh2[j] * sB[1][kk];
        }
        // NOTE: at frame boundary (k%8==0, k>0) the reg cache already holds the NEW
        // frame's wi2/wh2 — but L2(k-1) belongs to the OLD frame. Guard: reload old
        // frame's rows for this one interval.
        if ((k & 7) == 0) {
          size_t rb = (size_t)((k - 1) >> 3) * 1024 + row;
          const float* Wi = t1_Wih2 + rb * 256 + l16 * 16;
          const float* Wh = t1_Whh2 + rb * 256 + l16 * 16;
          a0 = 0.f; a1 = 0.f;
          #pragma unroll
          for (int j = 0; j < 16; j += 4) {
            float4 vi = *(const float4*)(Wi + j);
            float4 vh = *(const float4*)(Wh + j);
            int kk = l16 * 16 + j;
            a0 += vi.x*sM[0][kk] + vi.y*sM[0][kk+1] + vi.z*sM[0][kk+2] + vi.w*sM[0][kk+3]
                + vh.x*sB[0][kk] + vh.y*sB[0][kk+1] + vh.z*sB[0][kk+2] + vh.w*sB[0][kk+3];
            a1 += vi.x*sM[1][kk] + vi.y*sM[1][kk+1] + vi.z*sM[1][kk+2] + vi.w*sM[1][kk+3]
                + vh.x*sB[1][kk] + vh.y*sB[1][kk+1] + vh.z*sB[1][kk+2] + vh.w*sB[1][kk+3];
          }
        }
        #pragma unroll
        for (int o = 8; o; o >>= 1) {
          a0 += __shfl_down_sync(0xffffffffu, a0, o, 16);
          a1 += __shfl_down_sync(0xffffffffu, a1, o, 16);
        }
        if (l16 == 0) {
          float b2v = bs2;
          if ((k & 7) == 0) {  // old frame's bias
            size_t rb = (size_t)((k - 1) >> 3) * 1024 + row;
            b2v = __ldg(t1_bih2 + rb) + __ldg(t1_bhh2 + rb);
          }
          sg[grp][0] = a0 + b2v;
          sg[grp][1] = a1 + b2v;
        }
      }
      __syncthreads();
      if (k > 0 && tid < 16) {
        int s = k - 1;
        int cu = tid >> 1, bb = tid & 1, sin = s & 7;
        float gi = sg[cu*4+0][bb], gf = sg[cu*4+1][bb], gg = sg[cu*4+2][bb], go = sg[cu*4+3][bb];
        float c  = cell2[cu][bb];
        float cn = sigf(gf) * c + sigf(gi) * tanhfast(gg);
        float hn = sigf(go) * tanhfast(cn);
        cell2[cu][bb] = (sin == 7) ? 0.f : cn;
        int un = cta * 8 + cu;
        __stcg(&g_s.hB[p][bb][un], (sin == 7) ? cn : hn);
        if (sin == 7) __stcg(&g_s.fo[s >> 3][bb][un], hn);
      }
      gbar(cta, tid, ++ep);
    }
  }

  // ---------------- inp2 precompute ----------------
  for (int idx = tid; idx < 128 * 16; idx += 512) {
    int r = idx >> 4, q = idx & 15;
    int u = cta * 8 + (q >> 1), bb = q & 1;
    const float* Wr = W2hid + u * 256;
    const float* fr = &g_s.fo[r >> 2][bb][0];
    float acc = 0.f;
    #pragma unroll 4
    for (int j = 0; j < 256; j += 4) {
      float4 wv = *(const float4*)(Wr + j);
      acc += wv.x * __ldcg(fr + j)     + wv.y * __ldcg(fr + j + 1)
           + wv.z * __ldcg(fr + j + 2) + wv.w * __ldcg(fr + j + 3);
    }
    float xs = x[4 * r + bb] + x[4 * r + 2 + bb];
    __stcg(&g_s.inp2[r][bb][u], xs * W2in[u] + acc);
  }
  gbar(cta, tid, ++ep);

  // ---------------- tier 2: intervals j=0..128, pipelined, weight prefetch ----------------
  {
    const int t2b = grp & 1;
    const int rl  = grp >> 1;
    const int gate2 = rl & 3, ul = rl >> 2;
    const int unit2 = cta * 4 + ul;
    const int row2  = gate2 * 128 + unit2;

    float pf_i1[16], pf_h1[8], pf_i2[8], pf_h2[8];
    float pf_b1 = 0.f, pf_b2 = 0.f;

    // prefetch L1(0)
    {
      size_t base = (size_t)0 * 512 + row2;
      const float* Wi = t2_Wih1 + base * 256 + l16 * 16;
      const float* Wh = t2_Whh1 + base * 128 + l16 * 8;
      #pragma unroll
      for (int j = 0; j < 16; j += 4) { float4 v = *(const float4*)(Wi + j);
        pf_i1[j]=v.x; pf_i1[j+1]=v.y; pf_i1[j+2]=v.z; pf_i1[j+3]=v.w; }
      #pragma unroll
      for (int j = 0; j < 8; j += 4) { float4 v = *(const float4*)(Wh + j);
        pf_h1[j]=v.x; pf_h1[j+1]=v.y; pf_h1[j+2]=v.z; pf_h1[j+3]=v.w; }
      pf_b1 = __ldg(t2_bih1 + base) + __ldg(t2_bhh1 + base);
    }

    for (int j = 0; j <= 128; ++j) {
      const int p = j & 1, pn = p ^ 1;
      const int jj = (j < 128) ? j : 127;

      // stage
      { int b = tid >> 8, u = tid & 255; t2i[b][u] = __ldcg(&g_s.inp2[jj][b][u]); }
      if (tid < 256) { int b = tid >> 7, u = tid & 127;
        t2a[b][u]  = __ldcg(&g_s.h2A[pn][b][u]);
        t2m[b][u]  = __ldcg(&g_s.h2M[pn][b][u]);
        t2bp[b][u] = __ldcg(&g_s.h2B[pn][b][u]); }
      __syncthreads();

      // ---- L1(j) ----
      if (j < 128) {
        float a = 0.f;
        #pragma unroll
        for (int t = 0; t < 16; ++t) a += pf_i1[t] * t2i[t2b][l16 * 16 + t];
        #pragma unroll
        for (int t = 0; t < 8; ++t)  a += pf_h1[t] * t2a[t2b][l16 * 8 + t];
        #pragma unroll
        for (int o = 8; o; o >>= 1) a += __shfl_down_sync(0xffffffffu, a, o, 16);
        if (l16 == 0) sg[grp][0] = a + pf_b1;
      }
      __syncthreads();
      if (j < 128 && tid < 8) {
        int cu = tid >> 1, bb = tid & 1;
        float gi = sg[(cu*4+0)*2 + bb][0];
        float gg = sg[(cu*4+2)*2 + bb][0];
        float go = sg[(cu*4+3)*2 + bb][0];
        float cn = sigf(gi) * tanhfast(gg);     // cell starts at 0 each step
        float hn = sigf(go) * tanhfast(cn);
        int un = cta * 4 + cu;
        __stcg(&g_s.h2M[p][bb][un], hn);
        __stcg(&g_s.h2A[p][bb][un], cn);        // next step's h0 = cell
      }
      __syncthreads();

      // ---- L2(j-1) ----
      if (j > 0) {
        float a = 0.f;
        #pragma unroll
        for (int t = 0; t < 8; ++t) a += pf_i2[t] * t2m[t2b][l16 * 8 + t]
                                       + pf_h2[t] * t2bp[t2b][l16 * 8 + t];
        #pragma unroll
        for (int o = 8; o; o >>= 1) a += __shfl_down_sync(0xffffffffu, a, o, 16);
        if (l16 == 0) sg[grp][0] = a + pf_b2;
      }
      __syncthreads();
      if (j > 0 && tid < 8) {
        int r = j - 1;
        int cu = tid >> 1, bb = tid & 1;
        float gi = sg[(cu*4+0)*2 + bb][0];
        float gg = sg[(cu*4+2)*2 + bb][0];
        float go = sg[(cu*4+3)*2 + bb][0];
        float cn = sigf(gi) * tanhfast(gg);
        float hn = sigf(go) * tanhfast(cn);
        int un = cta * 4 + cu;
        __stcg(&g_s.h2B[p][bb][un], cn);        // next step's h0 = cell
        __stcg(&g_s.so[r][bb][un], hn);
      }

      // prefetch for interval j+1 (pure weight loads — issue before barrier to hide DRAM)
      {
        int nl1 = (j + 1 < 128) ? j + 1 : 127;   // L1(j+1)
        size_t b1a = (size_t)nl1 * 512 + row2;
        const float* Wi = t2_Wih1 + b1a * 256 + l16 * 16;
        const float* Wh = t2_Whh1 + b1a * 128 + l16 * 8;
        #pragma unroll
        for (int q = 0; q < 16; q += 4) { float4 v = *(const float4*)(Wi + q);
          pf_i1[q]=v.x; pf_i1[q+1]=v.y; pf_i1[q+2]=v.z; pf_i1[q+3]=v.w; }
        #pragma unroll
        for (int q = 0; q < 8; q += 4) { float4 v = *(const float4*)(Wh + q);
          pf_h1[q]=v.x; pf_h1[q+1]=v.y; pf_h1[q+2]=v.z; pf_h1[q+3]=v.w; }
        pf_b1 = __ldg(t2_bih1 + b1a) + __ldg(t2_bhh1 + b1a);

        int nl2 = (j < 128) ? j : 127;           // L2(j)
        size_t b2a = (size_t)nl2 * 512 + row2;
        const float* Wi2 = t2_Wih2 + b2a * 128 + l16 * 8;
        const float* Wh2 = t2_Whh2 + b2a * 128 + l16 * 8;
        #pragma unroll
        for (int q = 0; q < 8; q += 4) {
          float4 vi = *(const float4*)(Wi2 + q);
          float4 vh = *(const float4*)(Wh2 + q);
          pf_i2[q]=vi.x; pf_i2[q+1]=vi.y; pf_i2[q+2]=vi.z; pf_i2[q+3]=vi.w;
          pf_h2[q]=vh.x; pf_h2[q+1]=vh.y; pf_h2[q+2]=vh.z; pf_h2[q+3]=vh.w;
        }
        pf_b2 = __ldg(t2_bih2 + b2a) + __ldg(t2_bhh2 + b2a);
      }

      gbar(cta, tid, ++ep);

      // publish tier2 progress for tier3 consumers (so[0..j-1] now globally visible)
      if (j > 0 && cta == 0 && tid == 0) {
        __threadfence();
        *(volatile unsigned*)&g_s.so_done = (unsigned)j;
      }
    }
  }
}

extern "C" void kernel_launch(void* const* d_in, const int* in_sizes, int n_in,
                              void* d_out, int out_size) {
  const float* x        = (const float*)d_in[0];
  const float* t1_Wih1  = (const float*)d_in[1];
  const float* t1_Whh1  = (const float*)d_in[2];
  const float* t1_bih1  = (const float*)d_in[3];
  const float* t1_bhh1  = (const float*)d_in[4];
  const float* t1_Wih2  = (const float*)d_in[5];
  const float* t1_Whh2  = (const float*)d_in[6];
  const float* t1_bih2  = (const float*)d_in[7];
  const float* t1_bhh2  = (const float*)d_in[8];
  const float* W2in     = (const float*)d_in[9];
  const float* W2hid    = (const float*)d_in[10];
  const float* t2_Wih1  = (const float*)d_in[11];
  const float* t2_Whh1  = (const float*)d_in[12];
  const float* t2_bih1  = (const float*)d_in[13];
  const float* t2_bhh1  = (const float*)d_in[14];
  const float* t2_Wih2  = (const float*)d_in[15];
  const float* t2_Whh2  = (const float*)d_in[16];
  const float* t2_bih2  = (const float*)d_in[17];
  const float* t2_bhh2  = (const float*)d_in[18];
  const float* W3in     = (const float*)d_in[19];
  const float* W3hid    = (const float*)d_in[20];
  const float* t3_W1    = (const float*)d_in[21];
  const float* t3_b1    = (const float*)d_in[22];
  const float* t3_W2    = (const float*)d_in[23];
  const float* t3_b2    = (const float*)d_in[24];
  const float* t3_W3    = (const float*)d_in[25];
  const float* t3_b3    = (const float*)d_in[26];
  float* out = (float*)d_out;

  gen_init_kernel<<<1, 256>>>();
  gen_fused_kernel<<<NBLK, 512>>>(
      x, t1_Wih1, t1_Whh1, t1_bih1, t1_bhh1, t1_Wih2, t1_Whh2, t1_bih2, t1_bhh2,
      W2in, W2hid,
      t2_Wih1, t2_Whh1, t2_bih1, t2_bhh1, t2_Wih2, t2_Whh2, t2_bih2, t2_bhh2,
      W3in, W3hid, t3_W1, t3_b1, t3_W2, t3_b2, t3_W3, t3_b3, out);
}

// round 8
// speedup vs baseline: 1.5457x; 1.1237x over previous
#include <cuda_runtime.h>
#include <math.h>

#define NCHAIN 32
#define NT3    512
#define NBLK   (NCHAIN + NT3)

typedef unsigned long long u64;

// ---------------- persistent scratch: ALL cross-CTA data is tagged {tag:32|val:32} ----------------
struct Scratch {
  u64 tA[2][2][256];   // tier1 L1 carry   [parity][b][unit]
  u64 tM[2][2][256];   // tier1 L1 real h (feeds L2)
  u64 tB[2][2][256];   // tier1 L2 carry
  u64 t2A[2][2][128];  // tier2 L1 carry
  u64 t2M[2][2][128];  // tier2 L1 real h
  u64 t2B[2][2][128];  // tier2 L2 carry
  u64 fo[32][2][256];  // first_out (single-shot, tag 1)
  u64 inp2[128][2][256]; // tier2 inputs (single-shot, tag 1)
  u64 so[128][2][128]; // second_out (single-shot, tag 1)
};
__device__ Scratch g_s;

__device__ __forceinline__ float sigf(float v) { return 1.0f / (1.0f + __expf(-v)); }
__device__ __forceinline__ float tanhfast(float v) {
  float r; asm("tanh.approx.f32 %0, %1;" : "=f"(r) : "f"(v)); return r;
}

// publish tagged value (8B atomic store to L2)
__device__ __forceinline__ void stt(u64* p, float v, unsigned tag) {
  u64 w = ((u64)tag << 32) | (u64)__float_as_uint(v);
  asm volatile("st.global.cg.b64 [%0], %1;" :: "l"(p), "l"(w) : "memory");
}
// consume tagged value: load, and on tag miss back off briefly and retry.
// Tag+value travel in one atomic 8B word -> no fences needed anywhere.
__device__ __forceinline__ float ldt(const u64* p, unsigned tag) {
  u64 v;
  asm volatile("ld.global.cg.b64 %0, [%1];" : "=l"(v) : "l"(p) : "memory");
  while (__builtin_expect((unsigned)(v >> 32) != tag, 0)) {
    __nanosleep(32);
    asm volatile("ld.global.cg.b64 %0, [%1];" : "=l"(v) : "l"(p) : "memory");
  }
  return __uint_as_float((unsigned)v);
}
// consume with longer sleep backoff (tier3 waiters, may wait a long time)
__device__ __forceinline__ float ldt_sleep(const u64* p, unsigned tag) {
  u64 v;
  for (;;) {
    asm volatile("ld.global.cg.b64 %0, [%1];" : "=l"(v) : "l"(p) : "memory");
    if ((unsigned)(v >> 32) == tag) break;
    __nanosleep(200);
  }
  return __uint_as_float((unsigned)v);
}

// ---------------- init: clear ALL tags (and values) to 0 each launch ----------------
__global__ void gen_init_kernel() {
  u64* p = (u64*)&g_s;
  const int n = (int)(sizeof(Scratch) / 8);
  for (int i = blockIdx.x * blockDim.x + threadIdx.x; i < n; i += gridDim.x * blockDim.x)
    p[i] = 0ull;
}

// =====================================================================
// Fused kernel. Blocks 0..31: tier1+tier2 chain, barrier-free tagged
// dataflow (1 logical interval per LSTM step, zero fences). Blocks
// 32..543: tier3 MLPs gated on tagged second_out.
// =====================================================================
__global__ void __launch_bounds__(512) gen_fused_kernel(
  const float* __restrict__ x,
  const float* __restrict__ t1_Wih1, const float* __restrict__ t1_Whh1,
  const float* __restrict__ t1_bih1, const float* __restrict__ t1_bhh1,
  const float* __restrict__ t1_Wih2, const float* __restrict__ t1_Whh2,
  const float* __restrict__ t1_bih2, const float* __restrict__ t1_bhh2,
  const float* __restrict__ W2in,    const float* __restrict__ W2hid,
  const float* __restrict__ t2_Wih1, const float* __restrict__ t2_Whh1,
  const float* __restrict__ t2_bih1, const float* __restrict__ t2_bhh1,
  const float* __restrict__ t2_Wih2, const float* __restrict__ t2_Whh2,
  const float* __restrict__ t2_bih2, const float* __restrict__ t2_bhh2,
  const float* __restrict__ W3in,    const float* __restrict__ W3hid,
  const float* __restrict__ W1,      const float* __restrict__ b1,
  const float* __restrict__ W2,      const float* __restrict__ b2,
  const float* __restrict__ W3,      const float* __restrict__ b3,
  float* __restrict__ out)
{
  const int tid = threadIdx.x;

  if (blockIdx.x >= NCHAIN) {
    // ================== TIER 3 MLP path ==================
    const int s = blockIdx.x - NCHAIN;
    const int lane = tid & 31, w = tid >> 5;

    __shared__ float si[2][512];
    __shared__ float sh1[2][1024];
    __shared__ float sh2[2][1024];
    __shared__ float sq[2][128];
    __shared__ float yv[2];

    // wait on tagged second_out row s>>2 (self-validating; no fence needed)
    if (tid < 256) { int b = tid >> 7, u = tid & 127;
      sq[b][u] = ldt_sleep(&g_s.so[s >> 2][b][u], 1u); }
    __syncthreads();

    const float x0 = x[2 * s], x1 = x[2 * s + 1];

    // inp3[b][d] = x_b * W3in[d] + W3hid[d,:] . so[s/4][b]
    {
      const float* Wr = W3hid + tid * 128;
      float a0 = 0.f, a1 = 0.f;
      #pragma unroll 4
      for (int j = 0; j < 128; j += 4) {
        float4 v = *(const float4*)(Wr + j);
        a0 += v.x * sq[0][j] + v.y * sq[0][j+1] + v.z * sq[0][j+2] + v.w * sq[0][j+3];
        a1 += v.x * sq[1][j] + v.y * sq[1][j+1] + v.z * sq[1][j+2] + v.w * sq[1][j+3];
      }
      float wv = W3in[tid];
      si[0][tid] = x0 * wv + a0;
      si[1][tid] = x1 * wv + a1;
    }
    __syncthreads();

    // h1 = relu(W1[s] @ inp3 + b1[s])   (1024 x 512)
    {
      const float* W1s = W1 + (size_t)s * 1024 * 512;
      for (int o = w; o < 1024; o += 16) {
        const float* Wr = W1s + (size_t)o * 512;
        float a0 = 0.f, a1 = 0.f;
        #pragma unroll
        for (int k = 0; k < 4; ++k) {
          int ix = k * 128 + lane * 4;
          float4 v = *(const float4*)(Wr + ix);
          a0 += v.x * si[0][ix] + v.y * si[0][ix+1] + v.z * si[0][ix+2] + v.w * si[0][ix+3];
          a1 += v.x * si[1][ix] + v.y * si[1][ix+1] + v.z * si[1][ix+2] + v.w * si[1][ix+3];
        }
        #pragma unroll
        for (int off = 16; off; off >>= 1) {
          a0 += __shfl_down_sync(0xffffffffu, a0, off);
          a1 += __shfl_down_sync(0xffffffffu, a1, off);
        }
        if (lane == 0) {
          float bb = b1[s * 1024 + o];
          sh1[0][o] = fmaxf(a0 + bb, 0.f);
          sh1[1][o] = fmaxf(a1 + bb, 0.f);
        }
      }
    }
    __syncthreads();

    // h2 = relu(W2[s] @ h1 + b2[s])   (1024 x 1024)
    {
      const float* W2s = W2 + (size_t)s * 1024 * 1024;
      for (int o = w; o < 1024; o += 16) {
        const float* Wr = W2s + (size_t)o * 1024;
        float a0 = 0.f, a1 = 0.f;
        #pragma unroll
        for (int k = 0; k < 8; ++k) {
          int ix = k * 128 + lane * 4;
          float4 v = *(const float4*)(Wr + ix);
          a0 += v.x * sh1[0][ix] + v.y * sh1[0][ix+1] + v.z * sh1[0][ix+2] + v.w * sh1[0][ix+3];
          a1 += v.x * sh1[1][ix] + v.y * sh1[1][ix+1] + v.z * sh1[1][ix+2] + v.w * sh1[1][ix+3];
        }
        #pragma unroll
        for (int off = 16; off; off >>= 1) {
          a0 += __shfl_down_sync(0xffffffffu, a0, off);
          a1 += __shfl_down_sync(0xffffffffu, a1, off);
        }
        if (lane == 0) {
          float bb = b2[s * 1024 + o];
          sh2[0][o] = fmaxf(a0 + bb, 0.f);
          sh2[1][o] = fmaxf(a1 + bb, 0.f);
        }
      }
    }
    __syncthreads();

    // y[b] = relu(W3[s] . h2[b] + b3[s])
    if (w < 2) {
      const float* Wr = W3 + (size_t)s * 1024;
      float a = 0.f;
      for (int j = lane * 4; j < 1024; j += 128) {
        float4 v = *(const float4*)(Wr + j);
        a += v.x * sh2[w][j] + v.y * sh2[w][j+1] + v.z * sh2[w][j+2] + v.w * sh2[w][j+3];
      }
      #pragma unroll
      for (int off = 16; off; off >>= 1) a += __shfl_down_sync(0xffffffffu, a, off);
      if (lane == 0) yv[w] = fmaxf(a + b3[s], 0.f);
    }
    __syncthreads();

    if (tid == 0) out[s] = 1.0f / (1.0f + expf(yv[0] - yv[1]));  // softmax over batch, keep b=1
    return;
  }

  // ================== CHAIN path (blocks 0..31) ==================
  const int cta = blockIdx.x;
  const int grp = tid >> 4;     // 0..31
  const int l16 = tid & 15;

  __shared__ float sA[2][256];  // staged tA (L1 carry)
  __shared__ float sM[2][256];  // staged tM (L1 real h)
  __shared__ float sB[2][256];  // staged tB (L2 carry)
  __shared__ float sg[32][2];
  __shared__ float cell1[8][2], cell2[8][2];
  __shared__ float t2i[2][256], t2a[2][128], t2m[2][128], t2bp[2][128];

  if (tid < 16) { cell1[tid >> 1][tid & 1] = 0.f; cell2[tid >> 1][tid & 1] = 0.f; }

  // ---------------- tier 1: intervals k=0..256, pipelined L1(k) || L2(k-1) ----------------
  // Invariant: consumer at interval k reads parity (k-1)&1 expecting tag k.
  // Producer at interval k writes parity k&1 with tag k+1. Boundary: at k=0 the
  // L2 producer doesn't run, so we explicitly publish tB tag 1 = 0.0 (true initial carry).
  {
    const int uu = grp >> 2, gate = grp & 3;
    const int unit = cta * 8 + uu;
    const int row  = gate * 256 + unit;

    float w1r[16], wi2[16], wh2[16];    // per-frame register weight cache
    float bs1 = 0.f, wx1 = 0.f, bs2 = 0.f;

    for (int k = 0; k <= 256; ++k) {
      const int p = k & 1, pn = p ^ 1;

      if (k < 256 && (k & 7) == 0) {
        // frame start: load this frame's weight slices (reused 8 steps)
        size_t rb = (size_t)(k >> 3) * 1024 + row;
        const float* Wa = t1_Whh1 + rb * 256 + l16 * 16;
        const float* Wi = t1_Wih2 + rb * 256 + l16 * 16;
        const float* Wh = t1_Whh2 + rb * 256 + l16 * 16;
        #pragma unroll
        for (int j = 0; j < 16; j += 4) {
          float4 v = *(const float4*)(Wa + j); w1r[j]=v.x; w1r[j+1]=v.y; w1r[j+2]=v.z; w1r[j+3]=v.w;
          float4 a = *(const float4*)(Wi + j); wi2[j]=a.x; wi2[j+1]=a.y; wi2[j+2]=a.z; wi2[j+3]=a.w;
          float4 h = *(const float4*)(Wh + j); wh2[j]=h.x; wh2[j+1]=h.y; wh2[j+2]=h.z; wh2[j+3]=h.w;
        }
        bs1 = __ldg(t1_bih1 + rb) + __ldg(t1_bhh1 + rb);
        wx1 = __ldg(t1_Wih1 + rb);
        bs2 = __ldg(t1_bih2 + rb) + __ldg(t1_bhh2 + rb);
      }

      // stage tagged state published last interval (tag = k; k=0 hits init tag 0)
      { int b = tid >> 8, u = tid & 255;
        const unsigned tg = (unsigned)k;
        sA[b][u] = ldt(&g_s.tA[pn][b][u], tg);
        sM[b][u] = ldt(&g_s.tM[pn][b][u], tg);
        sB[b][u] = ldt(&g_s.tB[pn][b][u], tg); }
      __syncthreads();

      // ---- L1(k): Whh1_row . h1carry + x*Wih1 + biases ----
      if (k < 256) {
        float a0 = 0.f, a1 = 0.f;
        #pragma unroll
        for (int j = 0; j < 16; ++j) {
          int kk = l16 * 16 + j;
          a0 += w1r[j] * sA[0][kk];
          a1 += w1r[j] * sA[1][kk];
        }
        #pragma unroll
        for (int o = 8; o; o >>= 1) {
          a0 += __shfl_down_sync(0xffffffffu, a0, o, 16);
          a1 += __shfl_down_sync(0xffffffffu, a1, o, 16);
        }
        if (l16 == 0) {
          sg[grp][0] = a0 + bs1 + wx1 * x[2 * k + 0];
          sg[grp][1] = a1 + bs1 + wx1 * x[2 * k + 1];
        }
      }
      __syncthreads();
      if (k < 256 && tid < 16) {
        int cu = tid >> 1, bb = tid & 1, sin = k & 7;
        float gi = sg[cu*4+0][bb], gf = sg[cu*4+1][bb], gg = sg[cu*4+2][bb], go = sg[cu*4+3][bb];
        float c  = cell1[cu][bb];
        float cn = sigf(gf) * c + sigf(gi) * tanhfast(gg);
        float hn = sigf(go) * tanhfast(cn);
        cell1[cu][bb] = (sin == 7) ? 0.f : cn;
        int un = cta * 8 + cu;
        stt(&g_s.tM[p][bb][un], hn, (unsigned)(k + 1));
        stt(&g_s.tA[p][bb][un], (sin == 7) ? cn : hn, (unsigned)(k + 1));
        // BOUNDARY FIX: at k=0 the L2 producer is skipped, but interval k=1
        // consumes tB tag 1 from parity 0. Publish the true initial carry (0).
        if (k == 0) stt(&g_s.tB[0][bb][un], 0.f, 1u);
      }
      __syncthreads();

      // ---- L2(k-1): Wih2_row . h1real + Whh2_row . h2carry ----
      if (k > 0) {
        float a0 = 0.f, a1 = 0.f;
        #pragma unroll
        for (int j = 0; j < 16; ++j) {
          int kk = l16 * 16 + j;
          a0 += wi2[j] * sM[0][kk] + wh2[j] * sB[0][kk];
          a1 += wi2[j] * sM[1][kk] + wh2[j] * sB[1][kk];
        }
        // frame boundary: L2(k-1) belongs to the OLD frame; reload its rows
        if ((k & 7) == 0) {
          size_t rb = (size_t)((k - 1) >> 3) * 1024 + row;
          const float* Wi = t1_Wih2 + rb * 256 + l16 * 16;
          const float* Wh = t1_Whh2 + rb * 256 + l16 * 16;
          a0 = 0.f; a1 = 0.f;
          #pragma unroll
          for (int j = 0; j < 16; j += 4) {
            float4 vi = *(const float4*)(Wi + j);
            float4 vh = *(const float4*)(Wh + j);
            int kk = l16 * 16 + j;
            a0 += vi.x*sM[0][kk] + vi.y*sM[0][kk+1] + vi.z*sM[0][kk+2] + vi.w*sM[0][kk+3]
                + vh.x*sB[0][kk] + vh.y*sB[0][kk+1] + vh.z*sB[0][kk+2] + vh.w*sB[0][kk+3];
            a1 += vi.x*sM[1][kk] + vi.y*sM[1][kk+1] + vi.z*sM[1][kk+2] + vi.w*sM[1][kk+3]
                + vh.x*sB[1][kk] + vh.y*sB[1][kk+1] + vh.z*sB[1][kk+2] + vh.w*sB[1][kk+3];
          }
        }
        #pragma unroll
        for (int o = 8; o; o >>= 1) {
          a0 += __shfl_down_sync(0xffffffffu, a0, o, 16);
          a1 += __shfl_down_sync(0xffffffffu, a1, o, 16);
        }
        if (l16 == 0) {
          float b2v = bs2;
          if ((k & 7) == 0) {
            size_t rb = (size_t)((k - 1) >> 3) * 1024 + row;
            b2v = __ldg(t1_bih2 + rb) + __ldg(t1_bhh2 + rb);
          }
          sg[grp][0] = a0 + b2v;
          sg[grp][1] = a1 + b2v;
        }
      }
      __syncthreads();
      if (k > 0 && tid < 16) {
        int s = k - 1;
        int cu = tid >> 1, bb = tid & 1, sin = s & 7;
        float gi = sg[cu*4+0][bb], gf = sg[cu*4+1][bb], gg = sg[cu*4+2][bb], go = sg[cu*4+3][bb];
        float c  = cell2[cu][bb];
        float cn = sigf(gf) * c + sigf(gi) * tanhfast(gg);
        float hn = sigf(go) * tanhfast(cn);
        cell2[cu][bb] = (sin == 7) ? 0.f : cn;
        int un = cta * 8 + cu;
        stt(&g_s.tB[p][bb][un], (sin == 7) ? cn : hn, (unsigned)(k + 1));
        if (sin == 7) stt(&g_s.fo[s >> 3][bb][un], hn, 1u);
      }
      // no barrier: next interval's tagged polls enforce cross-CTA ordering
    }
  }
  __syncthreads();

  // ---------------- inp2 precompute: progressive staging of fo (tag 1) ----------------
  // inp2[r][b][u] = (x[4r+b]+x[4r+2+b]) * W2in[u] + W2hid[u,:] . fo[r/4][b]
  for (int g = 0; g < 32; ++g) {
    { int b = tid >> 8, u = tid & 255;
      sA[b][u] = ldt(&g_s.fo[g][b][u], 1u); }
    __syncthreads();
    {
      int e = tid >> 3, sub = tid & 7;      // e: 0..63 (entry), sub: slice of dot
      int r = 4 * g + (e >> 4);
      int q = e & 15;
      int u = cta * 8 + (q >> 1), bb = q & 1;
      const float* Wr = W2hid + u * 256 + sub * 32;
      const float* fv = &sA[bb][sub * 32];
      float acc = 0.f;
      #pragma unroll
      for (int j2 = 0; j2 < 32; j2 += 4) {
        float4 wv = *(const float4*)(Wr + j2);
        acc += wv.x * fv[j2] + wv.y * fv[j2+1] + wv.z * fv[j2+2] + wv.w * fv[j2+3];
      }
      #pragma unroll
      for (int o = 4; o; o >>= 1) acc += __shfl_down_sync(0xffffffffu, acc, o, 8);
      if (sub == 0) {
        float xs = x[4 * r + bb] + x[4 * r + 2 + bb];
        stt(&g_s.inp2[r][bb][u], xs * W2in[u] + acc, 1u);
      }
    }
    __syncthreads();
  }

  // ---------------- tier 2: intervals j=0..128, pipelined, weight prefetch ----------------
  {
    const int t2b = grp & 1;
    const int rl  = grp >> 1;
    const int gate2 = rl & 3, ul = rl >> 2;
    const int unit2 = cta * 4 + ul;
    const int row2  = gate2 * 128 + unit2;

    float pf_i1[16], pf_h1[8], pf_i2[8], pf_h2[8];
    float pf_b1 = 0.f, pf_b2 = 0.f;

    // prefetch L1(0)
    {
      size_t base = (size_t)0 * 512 + row2;
      const float* Wi = t2_Wih1 + base * 256 + l16 * 16;
      const float* Wh = t2_Whh1 + base * 128 + l16 * 8;
      #pragma unroll
      for (int j = 0; j < 16; j += 4) { float4 v = *(const float4*)(Wi + j);
        pf_i1[j]=v.x; pf_i1[j+1]=v.y; pf_i1[j+2]=v.z; pf_i1[j+3]=v.w; }
      #pragma unroll
      for (int j = 0; j < 8; j += 4) { float4 v = *(const float4*)(Wh + j);
        pf_h1[j]=v.x; pf_h1[j+1]=v.y; pf_h1[j+2]=v.z; pf_h1[j+3]=v.w; }
      pf_b1 = __ldg(t2_bih1 + base) + __ldg(t2_bhh1 + base);
    }

    for (int j = 0; j <= 128; ++j) {
      const int p = j & 1, pn = p ^ 1;
      const int jj = (j < 128) ? j : 127;

      // stage (tagged; j=0 hits init tag 0 = true zero initial state)
      { int b = tid >> 8, u = tid & 255; t2i[b][u] = ldt(&g_s.inp2[jj][b][u], 1u); }
      if (tid < 256) { int b = tid >> 7, u = tid & 127;
        const unsigned tg = (unsigned)j;
        t2a[b][u]  = ldt(&g_s.t2A[pn][b][u], tg);
        t2m[b][u]  = ldt(&g_s.t2M[pn][b][u], tg);
        t2bp[b][u] = ldt(&g_s.t2B[pn][b][u], tg); }
      __syncthreads();

      // ---- L1(j) ----
      if (j < 128) {
        float a = 0.f;
        #pragma unroll
        for (int t = 0; t < 16; ++t) a += pf_i1[t] * t2i[t2b][l16 * 16 + t];
        #pragma unroll
        for (int t = 0; t < 8; ++t)  a += pf_h1[t] * t2a[t2b][l16 * 8 + t];
        #pragma unroll
        for (int o = 8; o; o >>= 1) a += __shfl_down_sync(0xffffffffu, a, o, 16);
        if (l16 == 0) sg[grp][0] = a + pf_b1;
      }
      __syncthreads();
      if (j < 128 && tid < 8) {
        int cu = tid >> 1, bb = tid & 1;
        float gi = sg[(cu*4+0)*2 + bb][0];
        float gg = sg[(cu*4+2)*2 + bb][0];
        float go = sg[(cu*4+3)*2 + bb][0];
        float cn = sigf(gi) * tanhfast(gg);     // cell starts at 0 each step
        float hn = sigf(go) * tanhfast(cn);
        int un = cta * 4 + cu;
        stt(&g_s.t2M[p][bb][un], hn, (unsigned)(j + 1));
        stt(&g_s.t2A[p][bb][un], cn, (unsigned)(j + 1));   // next step's h0 = cell
        // BOUNDARY FIX: interval j=1 consumes t2B tag 1 from parity 0, but the
        // L2 producer is skipped at j=0. Publish the true initial carry (0).
        if (j == 0) stt(&g_s.t2B[0][bb][un], 0.f, 1u);
      }
      __syncthreads();

      // ---- L2(j-1) ----
      if (j > 0) {
        float a = 0.f;
        #pragma unroll
        for (int t = 0; t < 8; ++t) a += pf_i2[t] * t2m[t2b][l16 * 8 + t]
                                       + pf_h2[t] * t2bp[t2b][l16 * 8 + t];
        #pragma unroll
        for (int o = 8; o; o >>= 1) a += __shfl_down_sync(0xffffffffu, a, o, 16);
        if (l16 == 0) sg[grp][0] = a + pf_b2;
      }
      __syncthreads();
      if (j > 0 && tid < 8) {
        int r = j - 1;
        int cu = tid >> 1, bb = tid & 1;
        float gi = sg[(cu*4+0)*2 + bb][0];
        float gg = sg[(cu*4+2)*2 + bb][0];
        float go = sg[(cu*4+3)*2 + bb][0];
        float cn = sigf(gi) * tanhfast(gg);
        float hn = sigf(go) * tanhfast(cn);
        int un = cta * 4 + cu;
        stt(&g_s.t2B[p][bb][un], cn, (unsigned)(j + 1));   // next step's h0 = cell
        stt(&g_s.so[r][bb][un], hn, 1u);                   // second_out -> tier3
      }

      // prefetch for interval j+1 (pure weight loads; latency hidden by next polls)
      {
        int nl1 = (j + 1 < 128) ? j + 1 : 127;   // L1(j+1)
        size_t b1a = (size_t)nl1 * 512 + row2;
        const float* Wi = t2_Wih1 + b1a * 256 + l16 * 16;
        const float* Wh = t2_Whh1 + b1a * 128 + l16 * 8;
        #pragma unroll
        for (int q = 0; q < 16; q += 4) { float4 v = *(const float4*)(Wi + q);
          pf_i1[q]=v.x; pf_i1[q+1]=v.y; pf_i1[q+2]=v.z; pf_i1[q+3]=v.w; }
        #pragma unroll
        for (int q = 0; q < 8; q += 4) { float4 v = *(const float4*)(Wh + q);
          pf_h1[q]=v.x; pf_h1[q+1]=v.y; pf_h1[q+2]=v.z; pf_h1[q+3]=v.w; }
        pf_b1 = __ldg(t2_bih1 + b1a) + __ldg(t2_bhh1 + b1a);

        int nl2 = (j < 128) ? j : 127;           // L2(j)
        size_t b2a = (size_t)nl2 * 512 + row2;
        const float* Wi2 = t2_Wih2 + b2a * 128 + l16 * 8;
        const float* Wh2 = t2_Whh2 + b2a * 128 + l16 * 8;
        #pragma unroll
        for (int q = 0; q < 8; q += 4) {
          float4 vi = *(const float4*)(Wi2 + q);
          float4 vh = *(const float4*)(Wh2 + q);
          pf_i2[q]=vi.x; pf_i2[q+1]=vi.y; pf_i2[q+2]=vi.z; pf_i2[q+3]=vi.w;
          pf_h2[q]=vh.x; pf_h2[q+1]=vh.y; pf_h2[q+2]=vh.z; pf_h2[q+3]=vh.w;
        }
        pf_b2 = __ldg(t2_bih2 + b2a) + __ldg(t2_bhh2 + b2a);
      }
      __syncthreads();   // protect staged smem from next interval's overwrite
    }
  }
}

extern "C" void kernel_launch(void* const* d_in, const int* in_sizes, int n_in,
                              void* d_out, int out_size) {
  const float* x        = (const float*)d_in[0];
  const float* t1_Wih1  = (const float*)d_in[1];
  const float* t1_Whh1  = (const float*)d_in[2];
  const float* t1_bih1  = (const float*)d_in[3];
  const float* t1_bhh1  = (const float*)d_in[4];
  const float* t1_Wih2  = (const float*)d_in[5];
  const float* t1_Whh2  = (const float*)d_in[6];
  const float* t1_bih2  = (const float*)d_in[7];
  const float* t1_bhh2  = (const float*)d_in[8];
  const float* W2in     = (const float*)d_in[9];
  const float* W2hid    = (const float*)d_in[10];
  const float* t2_Wih1  = (const float*)d_in[11];
  const float* t2_Whh1  = (const float*)d_in[12];
  const float* t2_bih1  = (const float*)d_in[13];
  const float* t2_bhh1  = (const float*)d_in[14];
  const float* t2_Wih2  = (const float*)d_in[15];
  const float* t2_Whh2  = (const float*)d_in[16];
  const float* t2_bih2  = (const float*)d_in[17];
  const float* t2_bhh2  = (const float*)d_in[18];
  const float* W3in     = (const float*)d_in[19];
  const float* W3hid    = (const float*)d_in[20];
  const float* t3_W1    = (const float*)d_in[21];
  const float* t3_b1    = (const float*)d_in[22];
  const float* t3_W2    = (const float*)d_in[23];
  const float* t3_b2    = (const float*)d_in[24];
  const float* t3_W3    = (const float*)d_in[25];
  const float* t3_b3    = (const float*)d_in[26];
  float* out = (float*)d_out;

  gen_init_kernel<<<64, 512>>>();
  gen_fused_kernel<<<NBLK, 512>>>(
      x, t1_Wih1, t1_Whh1, t1_bih1, t1_bhh1, t1_Wih2, t1_Whh2, t1_bih2, t1_bhh2,
      W2in, W2hid,
      t2_Wih1, t2_Whh1, t2_bih1, t2_bhh1, t2_Wih2, t2_Whh2, t2_bih2, t2_bhh2,
      W3in, W3hid, t3_W1, t3_b1, t3_W2, t3_b2, t3_W3, t3_b3, out);
}

// round 15
// speedup vs baseline: 1.6552x; 1.0708x over previous
#include <cuda_runtime.h>
#include <math.h>

#define NCHAIN 32
#define NT3    512
#define NBLK   (NCHAIN + NT3)

typedef unsigned long long u64;

// ---------------- persistent scratch: ALL cross-CTA data is tagged {tag:32|val:32} ----------------
struct Scratch {
  u64 tA[2][2][256];   // tier1 L1 carry   [parity][b][unit]
  u64 tM[2][2][256];   // tier1 L1 real h (feeds L2)
  u64 tB[2][2][256];   // tier1 L2 carry
  u64 t2A[2][2][128];  // tier2 L1 carry
  u64 t2M[2][2][128];  // tier2 L1 real h
  u64 t2B[2][2][128];  // tier2 L2 carry
  u64 fo[32][2][256];  // first_out (single-shot, tag 1)
  u64 inp2[128][2][256]; // tier2 inputs (single-shot, tag 1)
  u64 so[128][2][128]; // second_out (single-shot, tag 1)
};
__device__ Scratch g_s;

__device__ __forceinline__ float sigf(float v) { return 1.0f / (1.0f + __expf(-v)); }
__device__ __forceinline__ float tanhfast(float v) {
  float r; asm("tanh.approx.f32 %0, %1;" : "=f"(r) : "f"(v)); return r;
}

// publish tagged value (8B atomic store to L2)
__device__ __forceinline__ void stt(u64* p, float v, unsigned tag) {
  u64 w = ((u64)tag << 32) | (u64)__float_as_uint(v);
  asm volatile("st.global.cg.b64 [%0], %1;" :: "l"(p), "l"(w) : "memory");
}
// single tagged load (no wait)
__device__ __forceinline__ u64 ld1(const u64* p) {
  u64 v;
  asm volatile("ld.global.cg.b64 %0, [%1];" : "=l"(v) : "l"(p) : "memory");
  return v;
}
// PURE SPIN consume: tight dependent-load loop, no nanosleep (chain CTAs only)
__device__ __forceinline__ float ldt(const u64* p, unsigned tag) {
  u64 v = ld1(p);
  while ((unsigned)(v >> 32) != tag) v = ld1(p);
  return __uint_as_float((unsigned)v);
}
// batched 3-way poll: three INDEPENDENT single-load asm statements (no output/input
// register aliasing possible, unlike a single multi-instruction asm block) issued
// back-to-back -> in-flight concurrently -> latency = max, not sum.
__device__ __forceinline__ void ldt3(const u64* pa, const u64* pb, const u64* pc,
                                     unsigned tag, float& ra, float& rb, float& rc) {
  u64 va = ld1(pa);
  u64 vb = ld1(pb);
  u64 vc = ld1(pc);
  while ((unsigned)(va >> 32) != tag) va = ld1(pa);
  while ((unsigned)(vb >> 32) != tag) vb = ld1(pb);
  while ((unsigned)(vc >> 32) != tag) vc = ld1(pc);
  ra = __uint_as_float((unsigned)va);
  rb = __uint_as_float((unsigned)vb);
  rc = __uint_as_float((unsigned)vc);
}
// sleep-backoff consume (tier3 waiters only — they wait a long time)
__device__ __forceinline__ float ldt_sleep(const u64* p, unsigned tag) {
  for (;;) {
    u64 v = ld1(p);
    if ((unsigned)(v >> 32) == tag) return __uint_as_float((unsigned)v);
    __nanosleep(400);
  }
}

// ---------------- init: clear ALL tags (and values) to 0 each launch ----------------
__global__ void gen_init_kernel() {
  u64* p = (u64*)&g_s;
  const int n = (int)(sizeof(Scratch) / 8);
  for (int i = blockIdx.x * blockDim.x + threadIdx.x; i < n; i += gridDim.x * blockDim.x)
    p[i] = 0ull;
}

// =====================================================================
// Fused kernel. Blocks 0..31: tier1+tier2 chain (R8 phase structure,
// tagged dataflow, no fences). Blocks 32..543: tier3 MLPs gated on
// tagged second_out.
// =====================================================================
__global__ void __launch_bounds__(512) gen_fused_kernel(
  const float* __restrict__ x,
  const float* __restrict__ t1_Wih1, const float* __restrict__ t1_Whh1,
  const float* __restrict__ t1_bih1, const float* __restrict__ t1_bhh1,
  const float* __restrict__ t1_Wih2, const float* __restrict__ t1_Whh2,
  const float* __restrict__ t1_bih2, const float* __restrict__ t1_bhh2,
  const float* __restrict__ W2in,    const float* __restrict__ W2hid,
  const float* __restrict__ t2_Wih1, const float* __restrict__ t2_Whh1,
  const float* __restrict__ t2_bih1, const float* __restrict__ t2_bhh1,
  const float* __restrict__ t2_Wih2, const float* __restrict__ t2_Whh2,
  const float* __restrict__ t2_bih2, const float* __restrict__ t2_bhh2,
  const float* __restrict__ W3in,    const float* __restrict__ W3hid,
  const float* __restrict__ W1,      const float* __restrict__ b1,
  const float* __restrict__ W2,      const float* __restrict__ b2,
  const float* __restrict__ W3,      const float* __restrict__ b3,
  float* __restrict__ out)
{
  const int tid = threadIdx.x;

  if (blockIdx.x >= NCHAIN) {
    // ================== TIER 3 MLP path ==================
    const int s = blockIdx.x - NCHAIN;
    const int lane = tid & 31, w = tid >> 5;

    __shared__ float si[2][512];
    __shared__ float sh1[2][1024];
    __shared__ float sh2[2][1024];
    __shared__ float sq[2][128];
    __shared__ float yv[2];

    // wait on tagged second_out row s>>2 (self-validating; no fence needed)
    if (tid < 256) { int b = tid >> 7, u = tid & 127;
      sq[b][u] = ldt_sleep(&g_s.so[s >> 2][b][u], 1u); }
    __syncthreads();

    const float x0 = x[2 * s], x1 = x[2 * s + 1];

    // inp3[b][d] = x_b * W3in[d] + W3hid[d,:] . so[s/4][b]
    {
      const float* Wr = W3hid + tid * 128;
      float a0 = 0.f, a1 = 0.f;
      #pragma unroll 4
      for (int j = 0; j < 128; j += 4) {
        float4 v = *(const float4*)(Wr + j);
        a0 += v.x * sq[0][j] + v.y * sq[0][j+1] + v.z * sq[0][j+2] + v.w * sq[0][j+3];
        a1 += v.x * sq[1][j] + v.y * sq[1][j+1] + v.z * sq[1][j+2] + v.w * sq[1][j+3];
      }
      float wv = W3in[tid];
      si[0][tid] = x0 * wv + a0;
      si[1][tid] = x1 * wv + a1;
    }
    __syncthreads();

    // h1 = relu(W1[s] @ inp3 + b1[s])   (1024 x 512)
    {
      const float* W1s = W1 + (size_t)s * 1024 * 512;
      for (int o = w; o < 1024; o += 16) {
        const float* Wr = W1s + (size_t)o * 512;
        float a0 = 0.f, a1 = 0.f;
        #pragma unroll
        for (int k = 0; k < 4; ++k) {
          int ix = k * 128 + lane * 4;
          float4 v = *(const float4*)(Wr + ix);
          a0 += v.x * si[0][ix] + v.y * si[0][ix+1] + v.z * si[0][ix+2] + v.w * si[0][ix+3];
          a1 += v.x * si[1][ix] + v.y * si[1][ix+1] + v.z * si[1][ix+2] + v.w * si[1][ix+3];
        }
        #pragma unroll
        for (int off = 16; off; off >>= 1) {
          a0 += __shfl_down_sync(0xffffffffu, a0, off);
          a1 += __shfl_down_sync(0xffffffffu, a1, off);
        }
        if (lane == 0) {
          float bb = b1[s * 1024 + o];
          sh1[0][o] = fmaxf(a0 + bb, 0.f);
          sh1[1][o] = fmaxf(a1 + bb, 0.f);
        }
      }
    }
    __syncthreads();

    // h2 = relu(W2[s] @ h1 + b2[s])   (1024 x 1024)
    {
      const float* W2s = W2 + (size_t)s * 1024 * 1024;
      for (int o = w; o < 1024; o += 16) {
        const float* Wr = W2s + (size_t)o * 1024;
        float a0 = 0.f, a1 = 0.f;
        #pragma unroll
        for (int k = 0; k < 8; ++k) {
          int ix = k * 128 + lane * 4;
          float4 v = *(const float4*)(Wr + ix);
          a0 += v.x * sh1[0][ix] + v.y * sh1[0][ix+1] + v.z * sh1[0][ix+2] + v.w * sh1[0][ix+3];
          a1 += v.x * sh1[1][ix] + v.y * sh1[1][ix+1] + v.z * sh1[1][ix+2] + v.w * sh1[1][ix+3];
        }
        #pragma unroll
        for (int off = 16; off; off >>= 1) {
          a0 += __shfl_down_sync(0xffffffffu, a0, off);
          a1 += __shfl_down_sync(0xffffffffu, a1, off);
        }
        if (lane == 0) {
          float bb = b2[s * 1024 + o];
          sh2[0][o] = fmaxf(a0 + bb, 0.f);
          sh2[1][o] = fmaxf(a1 + bb, 0.f);
        }
      }
    }
    __syncthreads();

    // y[b] = relu(W3[s] . h2[b] + b3[s])
    if (w < 2) {
      const float* Wr = W3 + (size_t)s * 1024;
      float a = 0.f;
      for (int j = lane * 4; j < 1024; j += 128) {
        float4 v = *(const float4*)(Wr + j);
        a += v.x * sh2[w][j] + v.y * sh2[w][j+1] + v.z * sh2[w][j+2] + v.w * sh2[w][j+3];
      }
      #pragma unroll
      for (int off = 16; off; off >>= 1) a += __shfl_down_sync(0xffffffffu, a, off);
      if (lane == 0) yv[w] = fmaxf(a + b3[s], 0.f);
    }
    __syncthreads();

    if (tid == 0) out[s] = 1.0f / (1.0f + expf(yv[0] - yv[1]));  // softmax over batch, keep b=1
    return;
  }

  // ================== CHAIN path (blocks 0..31) — R8 structure ==================
  const int cta = blockIdx.x;
  const int grp = tid >> 4;     // 0..31
  const int l16 = tid & 15;

  __shared__ float sA[2][256];  // staged tA (L1 carry)
  __shared__ float sM[2][256];  // staged tM (L1 real h)
  __shared__ float sB[2][256];  // staged tB (L2 carry)
  __shared__ float sg[32][2];
  __shared__ float cell1[8][2], cell2[8][2];
  __shared__ float t2i[2][256], t2a[2][128], t2m[2][128], t2bp[2][128];

  if (tid < 16) { cell1[tid >> 1][tid & 1] = 0.f; cell2[tid >> 1][tid & 1] = 0.f; }

  // ---------------- tier 1: intervals k=0..256, pipelined L1(k) || L2(k-1) ----------------
  // Consumer at interval k reads parity (k-1)&1 expecting tag k; producer at
  // interval k writes parity k&1 with tag k+1. k=0 boundary: tB tag 1 published explicitly.
  {
    const int uu = grp >> 2, gate = grp & 3;
    const int unit = cta * 8 + uu;
    const int row  = gate * 256 + unit;

    float w1r[16], wi2[16], wh2[16];    // per-frame register weight cache
    float bs1 = 0.f, wx1 = 0.f, bs2 = 0.f;

    for (int k = 0; k <= 256; ++k) {
      const int p = k & 1, pn = p ^ 1;

      if (k < 256 && (k & 7) == 0) {
        // frame start: load this frame's weight slices (reused 8 steps)
        size_t rb = (size_t)(k >> 3) * 1024 + row;
        const float* Wa = t1_Whh1 + rb * 256 + l16 * 16;
        const float* Wi = t1_Wih2 + rb * 256 + l16 * 16;
        const float* Wh = t1_Whh2 + rb * 256 + l16 * 16;
        #pragma unroll
        for (int j = 0; j < 16; j += 4) {
          float4 v = *(const float4*)(Wa + j); w1r[j]=v.x; w1r[j+1]=v.y; w1r[j+2]=v.z; w1r[j+3]=v.w;
          float4 a = *(const float4*)(Wi + j); wi2[j]=a.x; wi2[j+1]=a.y; wi2[j+2]=a.z; wi2[j+3]=a.w;
          float4 h = *(const float4*)(Wh + j); wh2[j]=h.x; wh2[j+1]=h.y; wh2[j+2]=h.z; wh2[j+3]=h.w;
        }
        bs1 = __ldg(t1_bih1 + rb) + __ldg(t1_bhh1 + rb);
        wx1 = __ldg(t1_Wih1 + rb);
        bs2 = __ldg(t1_bih2 + rb) + __ldg(t1_bhh2 + rb);
      }

      // stage tagged state published last interval (tag = k), batched spin poll
      { int b = tid >> 8, u = tid & 255;
        ldt3(&g_s.tA[pn][b][u], &g_s.tM[pn][b][u], &g_s.tB[pn][b][u],
             (unsigned)k, sA[b][u], sM[b][u], sB[b][u]); }
      __syncthreads();

      // ---- L1(k): Whh1_row . h1carry (+ x*Wih1 + biases) ----
      if (k < 256) {
        float a0 = 0.f, a1 = 0.f;
        #pragma unroll
        for (int j = 0; j < 16; ++j) {
          int kk = l16 * 16 + j;
          a0 += w1r[j] * sA[0][kk];
          a1 += w1r[j] * sA[1][kk];
        }
        #pragma unroll
        for (int o = 8; o; o >>= 1) {
          a0 += __shfl_down_sync(0xffffffffu, a0, o, 16);
          a1 += __shfl_down_sync(0xffffffffu, a1, o, 16);
        }
        if (l16 == 0) {
          sg[grp][0] = a0 + bs1 + wx1 * x[2 * k + 0];
          sg[grp][1] = a1 + bs1 + wx1 * x[2 * k + 1];
        }
      }
      __syncthreads();
      if (k < 256 && tid < 16) {
        int cu = tid >> 1, bb = tid & 1, sin = k & 7;
        float gi = sg[cu*4+0][bb], gf = sg[cu*4+1][bb], gg = sg[cu*4+2][bb], go = sg[cu*4+3][bb];
        float c  = cell1[cu][bb];
        float cn = sigf(gf) * c + sigf(gi) * tanhfast(gg);
        float hn = sigf(go) * tanhfast(cn);
        cell1[cu][bb] = (sin == 7) ? 0.f : cn;
        int un = cta * 8 + cu;
        stt(&g_s.tM[p][bb][un], hn, (unsigned)(k + 1));
        stt(&g_s.tA[p][bb][un], (sin == 7) ? cn : hn, (unsigned)(k + 1));
        // boundary: interval 1 consumes tB tag 1 from parity 0, never produced by L2
        if (k == 0) stt(&g_s.tB[0][bb][un], 0.f, 1u);
      }
      __syncthreads();

      // ---- L2(k-1): Wih2_row . h1real + Whh2_row . h2carry ----
      if (k > 0) {
        float a0 = 0.f, a1 = 0.f;
        #pragma unroll
        for (int j = 0; j < 16; ++j) {
          int kk = l16 * 16 + j;
          a0 += wi2[j] * sM[0][kk] + wh2[j] * sB[0][kk];
          a1 += wi2[j] * sM[1][kk] + wh2[j] * sB[1][kk];
        }
        // frame boundary: L2(k-1) belongs to the OLD frame; reload its rows
        if ((k & 7) == 0) {
          size_t rb = (size_t)((k - 1) >> 3) * 1024 + row;
          const float* Wi = t1_Wih2 + rb * 256 + l16 * 16;
          const float* Wh = t1_Whh2 + rb * 256 + l16 * 16;
          a0 = 0.f; a1 = 0.f;
          #pragma unroll
          for (int j = 0; j < 16; j += 4) {
            float4 vi = *(const float4*)(Wi + j);
            float4 vh = *(const float4*)(Wh + j);
            int kk = l16 * 16 + j;
            a0 += vi.x*sM[0][kk] + vi.y*sM[0][kk+1] + vi.z*sM[0][kk+2] + vi.w*sM[0][kk+3]
                + vh.x*sB[0][kk] + vh.y*sB[0][kk+1] + vh.z*sB[0][kk+2] + vh.w*sB[0][kk+3];
            a1 += vi.x*sM[1][kk] + vi.y*sM[1][kk+1] + vi.z*sM[1][kk+2] + vi.w*sM[1][kk+3]
                + vh.x*sB[1][kk] + vh.y*sB[1][kk+1] + vh.z*sB[1][kk+2] + vh.w*sB[1][kk+3];
          }
        }
        #pragma unroll
        for (int o = 8; o; o >>= 1) {
          a0 += __shfl_down_sync(0xffffffffu, a0, o, 16);
          a1 += __shfl_down_sync(0xffffffffu, a1, o, 16);
        }
        if (l16 == 0) {
          float b2v = bs2;
          if ((k & 7) == 0) {
            size_t rb = (size_t)((k - 1) >> 3) * 1024 + row;
            b2v = __ldg(t1_bih2 + rb) + __ldg(t1_bhh2 + rb);
          }
          sg[grp][0] = a0 + b2v;
          sg[grp][1] = a1 + b2v;
        }
      }
      __syncthreads();
      if (k > 0 && tid < 16) {
        int s = k - 1;
        int cu = tid >> 1, bb = tid & 1, sin = s & 7;
        float gi = sg[cu*4+0][bb], gf = sg[cu*4+1][bb], gg = sg[cu*4+2][bb], go = sg[cu*4+3][bb];
        float c  = cell2[cu][bb];
        float cn = sigf(gf) * c + sigf(gi) * tanhfast(gg);
        float hn = sigf(go) * tanhfast(cn);
        cell2[cu][bb] = (sin == 7) ? 0.f : cn;
        int un = cta * 8 + cu;
        stt(&g_s.tB[p][bb][un], (sin == 7) ? cn : hn, (unsigned)(k + 1));
        if (sin == 7) stt(&g_s.fo[s >> 3][bb][un], hn, 1u);
      }
      // no barrier: next interval's tagged polls enforce cross-CTA ordering
    }
  }
  __syncthreads();

  // ---------------- inp2 precompute: progressive staging of fo (tag 1) ----------------
  // inp2[r][b][u] = (x[4r+b]+x[4r+2+b]) * W2in[u] + W2hid[u,:] . fo[r/4][b]
  for (int g = 0; g < 32; ++g) {
    { int b = tid >> 8, u = tid & 255;
      sA[b][u] = ldt(&g_s.fo[g][b][u], 1u); }
    __syncthreads();
    {
      int e = tid >> 3, sub = tid & 7;      // e: 0..63 (entry), sub: slice of dot
      int r = 4 * g + (e >> 4);
      int q = e & 15;
      int u = cta * 8 + (q >> 1), bb = q & 1;
      const float* Wr = W2hid + u * 256 + sub * 32;
      const float* fv = &sA[bb][sub * 32];
      float acc = 0.f;
      #pragma unroll
      for (int j2 = 0; j2 < 32; j2 += 4) {
        float4 wv = *(const float4*)(Wr + j2);
        acc += wv.x * fv[j2] + wv.y * fv[j2+1] + wv.z * fv[j2+2] + wv.w * fv[j2+3];
      }
      #pragma unroll
      for (int o = 4; o; o >>= 1) acc += __shfl_down_sync(0xffffffffu, acc, o, 8);
      if (sub == 0) {
        float xs = x[4 * r + bb] + x[4 * r + 2 + bb];
        stt(&g_s.inp2[r][bb][u], xs * W2in[u] + acc, 1u);
      }
    }
    __syncthreads();
  }

  // ---------------- tier 2: intervals j=0..128, pipelined, weight prefetch ----------------
  {
    const int t2b = grp & 1;
    const int rl  = grp >> 1;
    const int gate2 = rl & 3, ul = rl >> 2;
    const int unit2 = cta * 4 + ul;
    const int row2  = gate2 * 128 + unit2;

    float pf_i1[16], pf_h1[8], pf_i2[8], pf_h2[8];
    float pf_b1 = 0.f, pf_b2 = 0.f;

    // prefetch L1(0)
    {
      size_t base = (size_t)0 * 512 + row2;
      const float* Wi = t2_Wih1 + base * 256 + l16 * 16;
      const float* Wh = t2_Whh1 + base * 128 + l16 * 8;
      #pragma unroll
      for (int j = 0; j < 16; j += 4) { float4 v = *(const float4*)(Wi + j);
        pf_i1[j]=v.x; pf_i1[j+1]=v.y; pf_i1[j+2]=v.z; pf_i1[j+3]=v.w; }
      #pragma unroll
      for (int j = 0; j < 8; j += 4) { float4 v = *(const float4*)(Wh + j);
        pf_h1[j]=v.x; pf_h1[j+1]=v.y; pf_h1[j+2]=v.z; pf_h1[j+3]=v.w; }
      pf_b1 = __ldg(t2_bih1 + base) + __ldg(t2_bhh1 + base);
    }

    for (int j = 0; j <= 128; ++j) {
      const int p = j & 1, pn = p ^ 1;
      const int jj = (j < 128) ? j : 127;

      // stage (tagged; j=0 hits init tag 0 = true zero initial state)
      { int b = tid >> 8, u = tid & 255; t2i[b][u] = ldt(&g_s.inp2[jj][b][u], 1u); }
      if (tid < 256) { int b = tid >> 7, u = tid & 127;
        ldt3(&g_s.t2A[pn][b][u], &g_s.t2M[pn][b][u], &g_s.t2B[pn][b][u],
             (unsigned)j, t2a[b][u], t2m[b][u], t2bp[b][u]); }
      __syncthreads();

      // ---- L1(j) ----
      if (j < 128) {
        float a = 0.f;
        #pragma unroll
        for (int t = 0; t < 16; ++t) a += pf_i1[t] * t2i[t2b][l16 * 16 + t];
        #pragma unroll
        for (int t = 0; t < 8; ++t)  a += pf_h1[t] * t2a[t2b][l16 * 8 + t];
        #pragma unroll
        for (int o = 8; o; o >>= 1) a += __shfl_down_sync(0xffffffffu, a, o, 16);
        if (l16 == 0) sg[grp][0] = a + pf_b1;
      }
      __syncthreads();
      if (j < 128 && tid < 8) {
        int cu = tid >> 1, bb = tid & 1;
        float gi = sg[(cu*4+0)*2 + bb][0];
        float gg = sg[(cu*4+2)*2 + bb][0];
        float go = sg[(cu*4+3)*2 + bb][0];
        float cn = sigf(gi) * tanhfast(gg);     // cell starts at 0 each step
        float hn = sigf(go) * tanhfast(cn);
        int un = cta * 4 + cu;
        stt(&g_s.t2M[p][bb][un], hn, (unsigned)(j + 1));
        stt(&g_s.t2A[p][bb][un], cn, (unsigned)(j + 1));   // next step's h0 = cell
        // boundary: interval 1 consumes t2B tag 1 from parity 0, never produced by L2
        if (j == 0) stt(&g_s.t2B[0][bb][un], 0.f, 1u);
      }
      __syncthreads();

      // ---- L2(j-1) ----
      if (j > 0) {
        float a = 0.f;
        #pragma unroll
        for (int t = 0; t < 8; ++t) a += pf_i2[t] * t2m[t2b][l16 * 8 + t]
                                       + pf_h2[t] * t2bp[t2b][l16 * 8 + t];
        #pragma unroll
        for (int o = 8; o; o >>= 1) a += __shfl_down_sync(0xffffffffu, a, o, 16);
        if (l16 == 0) sg[grp][0] = a + pf_b2;
      }
      __syncthreads();
      if (j > 0 && tid < 8) {
        int r = j - 1;
        int cu = tid >> 1, bb = tid & 1;
        float gi = sg[(cu*4+0)*2 + bb][0];
        float gg = sg[(cu*4+2)*2 + bb][0];
        float go = sg[(cu*4+3)*2 + bb][0];
        float cn = sigf(gi) * tanhfast(gg);
        float hn = sigf(go) * tanhfast(cn);
        int un = cta * 4 + cu;
        stt(&g_s.t2B[p][bb][un], cn, (unsigned)(j + 1));   // next step's h0 = cell
        stt(&g_s.so[r][bb][un], hn, 1u);                   // second_out -> tier3
      }

      // prefetch for interval j+1 (pure weight loads; latency hidden by next polls)
      {
        int nl1 = (j + 1 < 128) ? j + 1 : 127;   // L1(j+1)
        size_t b1a = (size_t)nl1 * 512 + row2;
        const float* Wi = t2_Wih1 + b1a * 256 + l16 * 16;
        const float* Wh = t2_Whh1 + b1a * 128 + l16 * 8;
        #pragma unroll
        for (int q = 0; q < 16; q += 4) { float4 v = *(const float4*)(Wi + q);
          pf_i1[q]=v.x; pf_i1[q+1]=v.y; pf_i1[q+2]=v.z; pf_i1[q+3]=v.w; }
        #pragma unroll
        for (int q = 0; q < 8; q += 4) { float4 v = *(const float4*)(Wh + q);
          pf_h1[q]=v.x; pf_h1[q+1]=v.y; pf_h1[q+2]=v.z; pf_h1[q+3]=v.w; }
        pf_b1 = __ldg(t2_bih1 + b1a) + __ldg(t2_bhh1 + b1a);

        int nl2 = (j < 128) ? j : 127;           // L2(j)
        size_t b2a = (size_t)nl2 * 512 + row2;
        const float* Wi2 = t2_Wih2 + b2a * 128 + l16 * 8;
        const float* Wh2 = t2_Whh2 + b2a * 128 + l16 * 8;
        #pragma unroll
        for (int q = 0; q < 8; q += 4) {
          float4 vi = *(const float4*)(Wi2 + q);
          float4 vh = *(const float4*)(Wh2 + q);
          pf_i2[q]=vi.x; pf_i2[q+1]=vi.y; pf_i2[q+2]=vi.z; pf_i2[q+3]=vi.w;
          pf_h2[q]=vh.x; pf_h2[q+1]=vh.y; pf_h2[q+2]=vh.z; pf_h2[q+3]=vh.w;
        }
        pf_b2 = __ldg(t2_bih2 + b2a) + __ldg(t2_bhh2 + b2a);
      }
      __syncthreads();   // protect staged smem from next interval's overwrite
    }
  }
}

extern "C" void kernel_launch(void* const* d_in, const int* in_sizes, int n_in,
                              void* d_out, int out_size) {
  const float* x        = (const float*)d_in[0];
  const float* t1_Wih1  = (const float*)d_in[1];
  const float* t1_Whh1  = (const float*)d_in[2];
  const float* t1_bih1  = (const float*)d_in[3];
  const float* t1_bhh1  = (const float*)d_in[4];
  const float* t1_Wih2  = (const float*)d_in[5];
  const float* t1_Whh2  = (const float*)d_in[6];
  const float* t1_bih2  = (const float*)d_in[7];
  const float* t1_bhh2  = (const float*)d_in[8];
  const float* W2in     = (const float*)d_in[9];
  const float* W2hid    = (const float*)d_in[10];
  const float* t2_Wih1  = (const float*)d_in[11];
  const float* t2_Whh1  = (const float*)d_in[12];
  const float* t2_bih1  = (const float*)d_in[13];
  const float* t2_bhh1  = (const float*)d_in[14];
  const float* t2_Wih2  = (const float*)d_in[15];
  const float* t2_Whh2  = (const float*)d_in[16];
  const float* t2_bih2  = (const float*)d_in[17];
  const float* t2_bhh2  = (const float*)d_in[18];
  const float* W3in     = (const float*)d_in[19];
  const float* W3hid    = (const float*)d_in[20];
  const float* t3_W1    = (const float*)d_in[21];
  const float* t3_b1    = (const float*)d_in[22];
  const float* t3_W2    = (const float*)d_in[23];
  const float* t3_b2    = (const float*)d_in[24];
  const float* t3_W3    = (const float*)d_in[25];
  const float* t3_b3    = (const float*)d_in[26];
  float* out = (float*)d_out;

  gen_init_kernel<<<64, 512>>>();
  gen_fused_kernel<<<NBLK, 512>>>(
      x, t1_Wih1, t1_Whh1, t1_bih1, t1_bhh1, t1_Wih2, t1_Whh2, t1_bih2, t1_bhh2,
      W2in, W2hid,
      t2_Wih1, t2_Whh1, t2_bih1, t2_bhh1, t2_Wih2, t2_Whh2, t2_bih2, t2_bhh2,
      W3in, W3hid, t3_W1, t3_b1, t3_W2, t3_b2, t3_W3, t3_b3, out);
}

// round 17
// speedup vs baseline: 2.5956x; 1.5682x over previous
#include <cuda_runtime.h>
#include <math.h>

#define NCHAIN 32
#define NT3    512
#define NBLK   (NCHAIN + NT3)

typedef unsigned long long u64;

// ---------------- persistent scratch: ALL cross-CTA data is tagged {tag:32|val:32} ----------------
struct Scratch {
  u64 tA[2][2][256];   // tier1 L1 carry   [parity][b][unit]
  u64 tM[2][2][256];   // tier1 L1 real h (feeds L2)
  u64 tB[2][2][256];   // tier1 L2 carry
  u64 t2A[2][2][128];  // tier2 L1 carry
  u64 t2M[2][2][128];  // tier2 L1 real h
  u64 t2B[2][2][128];  // tier2 L2 carry
  u64 fo[32][2][256];  // first_out (single-shot, tag 1)
  u64 inp2[128][2][256]; // tier2 inputs (single-shot, tag 1)
  u64 so[128][2][128]; // second_out (single-shot, tag 1)
};
__device__ Scratch g_s;

__device__ __forceinline__ float sigf(float v) { return 1.0f / (1.0f + __expf(-v)); }
__device__ __forceinline__ float tanhfast(float v) {
  float r; asm("tanh.approx.f32 %0, %1;" : "=f"(r) : "f"(v)); return r;
}

// publish tagged value (8B atomic store to L2)
__device__ __forceinline__ void stt(u64* p, float v, unsigned tag) {
  u64 w = ((u64)tag << 32) | (u64)__float_as_uint(v);
  asm volatile("st.global.cg.b64 [%0], %1;" :: "l"(p), "l"(w) : "memory");
}
// single tagged load (no wait)
__device__ __forceinline__ u64 ld1(const u64* p) {
  u64 v;
  asm volatile("ld.global.cg.b64 %0, [%1];" : "=l"(v) : "l"(p) : "memory");
  return v;
}
// PURE SPIN consume: tight dependent-load loop (chain CTAs only)
__device__ __forceinline__ float ldt(const u64* p, unsigned tag) {
  u64 v = ld1(p);
  while ((unsigned)(v >> 32) != tag) v = ld1(p);
  return __uint_as_float((unsigned)v);
}
// batched 3-way poll: three INDEPENDENT single-load asm statements (safe register
// allocation) issued back-to-back -> latency = max, not sum.
__device__ __forceinline__ void ldt3(const u64* pa, const u64* pb, const u64* pc,
                                     unsigned tag, float& ra, float& rb, float& rc) {
  u64 va = ld1(pa);
  u64 vb = ld1(pb);
  u64 vc = ld1(pc);
  while ((unsigned)(va >> 32) != tag) va = ld1(pa);
  while ((unsigned)(vb >> 32) != tag) vb = ld1(pb);
  while ((unsigned)(vc >> 32) != tag) vc = ld1(pc);
  ra = __uint_as_float((unsigned)va);
  rb = __uint_as_float((unsigned)vb);
  rc = __uint_as_float((unsigned)vc);
}
// sleep-backoff consume (tier3 waiters only — they wait a long time)
__device__ __forceinline__ float ldt_sleep(const u64* p, unsigned tag) {
  for (;;) {
    u64 v = ld1(p);
    if ((unsigned)(v >> 32) == tag) return __uint_as_float((unsigned)v);
    __nanosleep(400);
  }
}

// ---------------- init: clear ALL tags (and values) to 0 each launch ----------------
__global__ void gen_init_kernel() {
  u64* p = (u64*)&g_s;
  const int n = (int)(sizeof(Scratch) / 8);
  for (int i = blockIdx.x * blockDim.x + threadIdx.x; i < n; i += gridDim.x * blockDim.x)
    p[i] = 0ull;
}

// =====================================================================
// Fused kernel. Blocks 0..31: tier1+tier2 chain — 2-sync merged interval,
// conflict-free strided dots, tagged dataflow, no fences.
// Blocks 32..543: tier3 MLPs gated on tagged second_out.
// =====================================================================
__global__ void __launch_bounds__(512) gen_fused_kernel(
  const float* __restrict__ x,
  const float* __restrict__ t1_Wih1, const float* __restrict__ t1_Whh1,
  const float* __restrict__ t1_bih1, const float* __restrict__ t1_bhh1,
  const float* __restrict__ t1_Wih2, const float* __restrict__ t1_Whh2,
  const float* __restrict__ t1_bih2, const float* __restrict__ t1_bhh2,
  const float* __restrict__ W2in,    const float* __restrict__ W2hid,
  const float* __restrict__ t2_Wih1, const float* __restrict__ t2_Whh1,
  const float* __restrict__ t2_bih1, const float* __restrict__ t2_bhh1,
  const float* __restrict__ t2_Wih2, const float* __restrict__ t2_Whh2,
  const float* __restrict__ t2_bih2, const float* __restrict__ t2_bhh2,
  const float* __restrict__ W3in,    const float* __restrict__ W3hid,
  const float* __restrict__ W1,      const float* __restrict__ b1,
  const float* __restrict__ W2,      const float* __restrict__ b2,
  const float* __restrict__ W3,      const float* __restrict__ b3,
  float* __restrict__ out)
{
  const int tid = threadIdx.x;

  if (blockIdx.x >= NCHAIN) {
    // ================== TIER 3 MLP path ==================
    const int s = blockIdx.x - NCHAIN;
    const int lane = tid & 31, w = tid >> 5;

    __shared__ float si[2][512];
    __shared__ float sh1[2][1024];
    __shared__ float sh2[2][1024];
    __shared__ float sq[2][128];
    __shared__ float yv[2];

    if (tid < 256) { int b = tid >> 7, u = tid & 127;
      sq[b][u] = ldt_sleep(&g_s.so[s >> 2][b][u], 1u); }
    __syncthreads();

    const float x0 = x[2 * s], x1 = x[2 * s + 1];

    // inp3[b][d] = x_b * W3in[d] + W3hid[d,:] . so[s/4][b]
    {
      const float* Wr = W3hid + tid * 128;
      float a0 = 0.f, a1 = 0.f;
      #pragma unroll 4
      for (int j = 0; j < 128; j += 4) {
        float4 v = *(const float4*)(Wr + j);
        a0 += v.x * sq[0][j] + v.y * sq[0][j+1] + v.z * sq[0][j+2] + v.w * sq[0][j+3];
        a1 += v.x * sq[1][j] + v.y * sq[1][j+1] + v.z * sq[1][j+2] + v.w * sq[1][j+3];
      }
      float wv = W3in[tid];
      si[0][tid] = x0 * wv + a0;
      si[1][tid] = x1 * wv + a1;
    }
    __syncthreads();

    // h1 = relu(W1[s] @ inp3 + b1[s])   (1024 x 512)
    {
      const float* W1s = W1 + (size_t)s * 1024 * 512;
      for (int o = w; o < 1024; o += 16) {
        const float* Wr = W1s + (size_t)o * 512;
        float a0 = 0.f, a1 = 0.f;
        #pragma unroll
        for (int k = 0; k < 4; ++k) {
          int ix = k * 128 + lane * 4;
          float4 v = *(const float4*)(Wr + ix);
          a0 += v.x * si[0][ix] + v.y * si[0][ix+1] + v.z * si[0][ix+2] + v.w * si[0][ix+3];
          a1 += v.x * si[1][ix] + v.y * si[1][ix+1] + v.z * si[1][ix+2] + v.w * si[1][ix+3];
        }
        #pragma unroll
        for (int off = 16; off; off >>= 1) {
          a0 += __shfl_down_sync(0xffffffffu, a0, off);
          a1 += __shfl_down_sync(0xffffffffu, a1, off);
        }
        if (lane == 0) {
          float bb = b1[s * 1024 + o];
          sh1[0][o] = fmaxf(a0 + bb, 0.f);
          sh1[1][o] = fmaxf(a1 + bb, 0.f);
        }
      }
    }
    __syncthreads();

    // h2 = relu(W2[s] @ h1 + b2[s])   (1024 x 1024)
    {
      const float* W2s = W2 + (size_t)s * 1024 * 1024;
      for (int o = w; o < 1024; o += 16) {
        const float* Wr = W2s + (size_t)o * 1024;
        float a0 = 0.f, a1 = 0.f;
        #pragma unroll
        for (int k = 0; k < 8; ++k) {
          int ix = k * 128 + lane * 4;
          float4 v = *(const float4*)(Wr + ix);
          a0 += v.x * sh1[0][ix] + v.y * sh1[0][ix+1] + v.z * sh1[0][ix+2] + v.w * sh1[0][ix+3];
          a1 += v.x * sh1[1][ix] + v.y * sh1[1][ix+1] + v.z * sh1[1][ix+2] + v.w * sh1[1][ix+3];
        }
        #pragma unroll
        for (int off = 16; off; off >>= 1) {
          a0 += __shfl_down_sync(0xffffffffu, a0, off);
          a1 += __shfl_down_sync(0xffffffffu, a1, off);
        }
        if (lane == 0) {
          float bb = b2[s * 1024 + o];
          sh2[0][o] = fmaxf(a0 + bb, 0.f);
          sh2[1][o] = fmaxf(a1 + bb, 0.f);
        }
      }
    }
    __syncthreads();

    // y[b] = relu(W3[s] . h2[b] + b3[s])
    if (w < 2) {
      const float* Wr = W3 + (size_t)s * 1024;
      float a = 0.f;
      for (int j = lane * 4; j < 1024; j += 128) {
        float4 v = *(const float4*)(Wr + j);
        a += v.x * sh2[w][j] + v.y * sh2[w][j+1] + v.z * sh2[w][j+2] + v.w * sh2[w][j+3];
      }
      #pragma unroll
      for (int off = 16; off; off >>= 1) a += __shfl_down_sync(0xffffffffu, a, off);
      if (lane == 0) yv[w] = fmaxf(a + b3[s], 0.f);
    }
    __syncthreads();

    if (tid == 0) out[s] = 1.0f / (1.0f + expf(yv[0] - yv[1]));  // softmax over batch, keep b=1
    return;
  }

  // ================== CHAIN path (blocks 0..31) ==================
  const int cta = blockIdx.x;
  const int grp = tid >> 4;     // 0..31
  const int l16 = tid & 15;

  __shared__ float sx[1024];    // staged x
  __shared__ float sA[2][256];  // staged tA (L1 carry)
  __shared__ float sM[2][256];  // staged tM (L1 real h)
  __shared__ float sB[2][256];  // staged tB (L2 carry)
  __shared__ float sg1[32][2];  // L1 gate pre-activations
  __shared__ float sg2[32][2];  // L2 gate pre-activations
  __shared__ float cell1[8][2], cell2[8][2];
  __shared__ float t2i[2 * 272];                       // padded: batch offset 272
  __shared__ float t2a[2 * 144], t2m[2 * 144], t2bp[2 * 144];  // padded: 144

  for (int i = tid; i < 1024; i += 512) sx[i] = x[i];
  if (tid < 16) { cell1[tid >> 1][tid & 1] = 0.f; cell2[tid >> 1][tid & 1] = 0.f; }
  __syncthreads();

  // ---------------- tier 1: intervals k=0..256, merged L1(k) || L2(k-1), 2 syncs ----------------
  // Consumer at interval k reads parity (k-1)&1 expecting tag k; producer at
  // interval k writes parity k&1 with tag k+1. Strided dots: thread l16 owns
  // elements {j*16 + l16} -> all lanes read consecutive smem words (conflict-free).
  {
    const int uu = grp >> 2, gate = grp & 3;
    const int unit = cta * 8 + uu;
    const int row  = gate * 256 + unit;

    float w1r[16], wi2[16], wh2[16];  // strided register weight caches
    float bs1 = 0.f, wx1 = 0.f, bs2 = 0.f;

    for (int k = 0; k <= 256; ++k) {
      const int p = k & 1, pn = p ^ 1;
      const bool fstart = (k < 256) && ((k & 7) == 0);

      if (fstart) {
        // frame start: load NEW frame's L1 weights (used this interval's P1).
        // L2 weights (wi2/wh2) stay OLD until post-P1 (L2(k-1) is old-frame).
        size_t rb = (size_t)(k >> 3) * 1024 + row;
        const float* Wa = t1_Whh1 + rb * 256 + l16;
        #pragma unroll
        for (int j = 0; j < 16; ++j) w1r[j] = __ldg(Wa + j * 16);
        bs1 = __ldg(t1_bih1 + rb) + __ldg(t1_bhh1 + rb);
        wx1 = __ldg(t1_Wih1 + rb);
      }

      // P0: stage tagged state (tag = k), batched spin poll
      { int b = tid >> 8, u = tid & 255;
        ldt3(&g_s.tA[pn][b][u], &g_s.tM[pn][b][u], &g_s.tB[pn][b][u],
             (unsigned)k, sA[b][u], sM[b][u], sB[b][u]); }
      __syncthreads();

      // P1: L1(k) and L2(k-1) gates, strided conflict-free dots
      {
        float a0 = 0.f, a1 = 0.f, c0 = 0.f, c1 = 0.f;
        if (k < 256) {
          #pragma unroll
          for (int j = 0; j < 16; ++j) {
            int kk = j * 16 + l16;
            a0 += w1r[j] * sA[0][kk];
            a1 += w1r[j] * sA[1][kk];
          }
        }
        if (k > 0) {
          #pragma unroll
          for (int j = 0; j < 16; ++j) {
            int kk = j * 16 + l16;
            c0 += wi2[j] * sM[0][kk] + wh2[j] * sB[0][kk];
            c1 += wi2[j] * sM[1][kk] + wh2[j] * sB[1][kk];
          }
        }
        #pragma unroll
        for (int o = 8; o; o >>= 1) {
          a0 += __shfl_down_sync(0xffffffffu, a0, o, 16);
          a1 += __shfl_down_sync(0xffffffffu, a1, o, 16);
          c0 += __shfl_down_sync(0xffffffffu, c0, o, 16);
          c1 += __shfl_down_sync(0xffffffffu, c1, o, 16);
        }
        if (l16 == 0) {
          if (k < 256) {
            sg1[grp][0] = a0 + bs1 + wx1 * sx[2 * k + 0];
            sg1[grp][1] = a1 + bs1 + wx1 * sx[2 * k + 1];
          }
          if (k > 0) {
            sg2[grp][0] = c0 + bs2;   // bs2 still OLD frame at boundary (correct)
            sg2[grp][1] = c1 + bs2;
          }
        }
      }
      __syncthreads();

      // P2: cell updates + tagged publishes (16 threads); no trailing sync.
      if (tid < 16) {
        int cu = tid >> 1, bb = tid & 1;
        int un = cta * 8 + cu;
        if (k < 256) {
          int sin = k & 7;
          float gi = sg1[cu*4+0][bb], gf = sg1[cu*4+1][bb], gg = sg1[cu*4+2][bb], go = sg1[cu*4+3][bb];
          float c  = cell1[cu][bb];
          float cn = sigf(gf) * c + sigf(gi) * tanhfast(gg);
          float hn = sigf(go) * tanhfast(cn);
          cell1[cu][bb] = (sin == 7) ? 0.f : cn;
          stt(&g_s.tM[p][bb][un], hn, (unsigned)(k + 1));
          stt(&g_s.tA[p][bb][un], (sin == 7) ? cn : hn, (unsigned)(k + 1));
          // boundary: interval 1 consumes tB tag 1 from parity 0, never produced by L2
          if (k == 0) stt(&g_s.tB[0][bb][un], 0.f, 1u);
        }
        if (k > 0) {
          int s = k - 1, sin = s & 7;
          float gi = sg2[cu*4+0][bb], gf = sg2[cu*4+1][bb], gg = sg2[cu*4+2][bb], go = sg2[cu*4+3][bb];
          float c  = cell2[cu][bb];
          float cn = sigf(gf) * c + sigf(gi) * tanhfast(gg);
          float hn = sigf(go) * tanhfast(cn);
          cell2[cu][bb] = (sin == 7) ? 0.f : cn;
          stt(&g_s.tB[p][bb][un], (sin == 7) ? cn : hn, (unsigned)(k + 1));
          if (sin == 7) stt(&g_s.fo[s >> 3][bb][un], hn, 1u);
        }
      }

      // post-P1: load NEW frame's L2 weights (first used next interval)
      if (fstart) {
        size_t rb = (size_t)(k >> 3) * 1024 + row;
        const float* Wi = t1_Wih2 + rb * 256 + l16;
        const float* Wh = t1_Whh2 + rb * 256 + l16;
        #pragma unroll
        for (int j = 0; j < 16; ++j) {
          wi2[j] = __ldg(Wi + j * 16);
          wh2[j] = __ldg(Wh + j * 16);
        }
        bs2 = __ldg(t1_bih2 + rb) + __ldg(t1_bhh2 + rb);
      }
      // no trailing sync: next P0's tagged polls self-synchronize
    }
  }
  __syncthreads();

  // ---------------- inp2 precompute: progressive staging of fo (tag 1) ----------------
  // inp2[r][b][u] = (x[4r+b]+x[4r+2+b]) * W2in[u] + W2hid[u,:] . fo[r/4][b]
  for (int g = 0; g < 32; ++g) {
    { int b = tid >> 8, u = tid & 255;
      sA[b][u] = ldt(&g_s.fo[g][b][u], 1u); }
    __syncthreads();
    {
      int e = tid >> 3, sub = tid & 7;      // e: 0..63 (entry), sub: slice of dot
      int r = 4 * g + (e >> 4);
      int q = e & 15;
      int u = cta * 8 + (q >> 1), bb = q & 1;
      const float* Wr = W2hid + u * 256 + sub * 32;
      const float* fv = &sA[bb][sub * 32];
      float acc = 0.f;
      #pragma unroll
      for (int j2 = 0; j2 < 32; j2 += 4) {
        float4 wv = *(const float4*)(Wr + j2);
        acc += wv.x * fv[j2] + wv.y * fv[j2+1] + wv.z * fv[j2+2] + wv.w * fv[j2+3];
      }
      #pragma unroll
      for (int o = 4; o; o >>= 1) acc += __shfl_down_sync(0xffffffffu, acc, o, 8);
      if (sub == 0) {
        float xs = sx[4 * r + bb] + sx[4 * r + 2 + bb];
        stt(&g_s.inp2[r][bb][u], xs * W2in[u] + acc, 1u);
      }
    }
    __syncthreads();
  }

  // ---------------- tier 2: intervals j=0..128, merged L1(j) || L2(j-1), 2 syncs ----------------
  {
    const int t2b = grp & 1;
    const int rl  = grp >> 1;
    const int gate2 = rl & 3, ul = rl >> 2;
    const int unit2 = cta * 4 + ul;
    const int row2  = gate2 * 128 + unit2;

    float pf_i1[16], pf_h1[8], pf_i2[8], pf_h2[8];
    float pf_b1 = 0.f, pf_b2 = 0.f;

    // prefetch L1(0) — strided
    {
      size_t base = (size_t)row2;
      const float* Wi = t2_Wih1 + base * 256 + l16;
      const float* Wh = t2_Whh1 + base * 128 + l16;
      #pragma unroll
      for (int j = 0; j < 16; ++j) pf_i1[j] = __ldg(Wi + j * 16);
      #pragma unroll
      for (int j = 0; j < 8; ++j)  pf_h1[j] = __ldg(Wh + j * 16);
      pf_b1 = __ldg(t2_bih1 + base) + __ldg(t2_bhh1 + base);
    }

    for (int j = 0; j <= 128; ++j) {
      const int p = j & 1, pn = p ^ 1;
      const int jj = (j < 128) ? j : 127;

      // P0: stage (tagged; j=0 hits init tag 0 = true zero initial state)
      { int b = tid >> 8, u = tid & 255;
        t2i[b * 272 + u] = ldt(&g_s.inp2[jj][b][u], 1u); }
      if (tid < 256) { int b = tid >> 7, u = tid & 127;
        ldt3(&g_s.t2A[pn][b][u], &g_s.t2M[pn][b][u], &g_s.t2B[pn][b][u],
             (unsigned)j, t2a[b * 144 + u], t2m[b * 144 + u], t2bp[b * 144 + u]); }
      __syncthreads();

      // P1: L1(j) and L2(j-1) gates, strided conflict-free dots
      {
        float a = 0.f, c = 0.f;
        if (j < 128) {
          #pragma unroll
          for (int t = 0; t < 16; ++t) a += pf_i1[t] * t2i[t2b * 272 + t * 16 + l16];
          #pragma unroll
          for (int t = 0; t < 8; ++t)  a += pf_h1[t] * t2a[t2b * 144 + t * 16 + l16];
        }
        if (j > 0) {
          #pragma unroll
          for (int t = 0; t < 8; ++t) c += pf_i2[t] * t2m[t2b * 144 + t * 16 + l16]
                                         + pf_h2[t] * t2bp[t2b * 144 + t * 16 + l16];
        }
        #pragma unroll
        for (int o = 8; o; o >>= 1) {
          a += __shfl_down_sync(0xffffffffu, a, o, 16);
          c += __shfl_down_sync(0xffffffffu, c, o, 16);
        }
        if (l16 == 0) {
          if (j < 128) sg1[grp][0] = a + pf_b1;
          if (j > 0)   sg2[grp][0] = c + pf_b2;
        }
      }
      __syncthreads();

      // P2: cells + publishes (8 threads); no trailing sync.
      if (tid < 8) {
        int cu = tid >> 1, bb = tid & 1;
        int un = cta * 4 + cu;
        if (j < 128) {
          float gi = sg1[(cu*4+0)*2 + bb][0];
          float gg = sg1[(cu*4+2)*2 + bb][0];
          float go = sg1[(cu*4+3)*2 + bb][0];
          float cn = sigf(gi) * tanhfast(gg);     // cell starts at 0 each step
          float hn = sigf(go) * tanhfast(cn);
          stt(&g_s.t2M[p][bb][un], hn, (unsigned)(j + 1));
          stt(&g_s.t2A[p][bb][un], cn, (unsigned)(j + 1));   // next step's h0 = cell
          if (j == 0) stt(&g_s.t2B[0][bb][un], 0.f, 1u);     // boundary publish
        }
        if (j > 0) {
          int r = j - 1;
          float gi = sg2[(cu*4+0)*2 + bb][0];
          float gg = sg2[(cu*4+2)*2 + bb][0];
          float go = sg2[(cu*4+3)*2 + bb][0];
          float cn = sigf(gi) * tanhfast(gg);
          float hn = sigf(go) * tanhfast(cn);
          stt(&g_s.t2B[p][bb][un], cn, (unsigned)(j + 1));   // next step's h0 = cell
          stt(&g_s.so[r][bb][un], hn, 1u);                   // second_out -> tier3
        }
      }

      // prefetch for interval j+1 (strided; registers only)
      {
        int nl1 = (j + 1 < 128) ? j + 1 : 127;   // L1(j+1)
        size_t b1a = (size_t)nl1 * 512 + row2;
        const float* Wi = t2_Wih1 + b1a * 256 + l16;
        const float* Wh = t2_Whh1 + b1a * 128 + l16;
        #pragma unroll
        for (int q = 0; q < 16; ++q) pf_i1[q] = __ldg(Wi + q * 16);
        #pragma unroll
        for (int q = 0; q < 8; ++q)  pf_h1[q] = __ldg(Wh + q * 16);
        pf_b1 = __ldg(t2_bih1 + b1a) + __ldg(t2_bhh1 + b1a);

        int nl2 = (j < 128) ? j : 127;           // L2(j)
        size_t b2a = (size_t)nl2 * 512 + row2;
        const float* Wi2 = t2_Wih2 + b2a * 128 + l16;
        const float* Wh2 = t2_Whh2 + b2a * 128 + l16;
        #pragma unroll
        for (int q = 0; q < 8; ++q) {
          pf_i2[q] = __ldg(Wi2 + q * 16);
          pf_h2[q] = __ldg(Wh2 + q * 16);
        }
        pf_b2 = __ldg(t2_bih2 + b2a) + __ldg(t2_bhh2 + b2a);
      }
      // no trailing sync: next P0's tagged polls self-synchronize
    }
  }
}

extern "C" void kernel_launch(void* const* d_in, const int* in_sizes, int n_in,
                              void* d_out, int out_size) {
  const float* x        = (const float*)d_in[0];
  const float* t1_Wih1  = (const float*)d_in[1];
  const float* t1_Whh1  = (const float*)d_in[2];
  const float* t1_bih1  = (const float*)d_in[3];
  const float* t1_bhh1  = (const float*)d_in[4];
  const float* t1_Wih2  = (const float*)d_in[5];
  const float* t1_Whh2  = (const float*)d_in[6];
  const float* t1_bih2  = (const float*)d_in[7];
  const float* t1_bhh2  = (const float*)d_in[8];
  const float* W2in     = (const float*)d_in[9];
  const float* W2hid    = (const float*)d_in[10];
  const float* t2_Wih1  = (const float*)d_in[11];
  const float* t2_Whh1  = (const float*)d_in[12];
  const float* t2_bih1  = (const float*)d_in[13];
  const float* t2_bhh1  = (const float*)d_in[14];
  const float* t2_Wih2  = (const float*)d_in[15];
  const float* t2_Whh2  = (const float*)d_in[16];
  const float* t2_bih2  = (const float*)d_in[17];
  const float* t2_bhh2  = (const float*)d_in[18];
  const float* W3in     = (const float*)d_in[19];
  const float* W3hid    = (const float*)d_in[20];
  const float* t3_W1    = (const float*)d_in[21];
  const float* t3_b1    = (const float*)d_in[22];
  const float* t3_W2    = (const float*)d_in[23];
  const float* t3_b2    = (const float*)d_in[24];
  const float* t3_W3    = (const float*)d_in[25];
  const float* t3_b3    = (const float*)d_in[26];
  float* out = (float*)d_out;

  gen_init_kernel<<<64, 512>>>();
  gen_fused_kernel<<<NBLK, 512>>>(
      x, t1_Wih1, t1_Whh1, t1_bih1, t1_bhh1, t1_Wih2, t1_Whh2, t1_bih2, t1_bhh2,
      W2in, W2hid,
      t2_Wih1, t2_Whh1, t2_bih1, t2_bhh1, t2_Wih2, t2_Whh2, t2_bih2, t2_bhh2,
      W3in, W3hid, t3_W1, t3_b1, t3_W2, t3_b2, t3_W3, t3_b3, out);
}